// round 10
// baseline (speedup 1.0000x reference)
#include <cuda_runtime.h>
#include <cuda_bf16.h>
#include <cstdint>

// Problem constants (match reference_code)
#define IN_C    128
#define HID_C   256
#define OUT_C   128
#define N_NODES 50000
#define N_EDGES 600000

// ---------------------------------------------------------------------------
// Scratch (no cudaMalloc allowed): device globals
// ---------------------------------------------------------------------------
__device__ int g_cnt_int  [N_NODES];
__device__ int g_row_start[N_NODES + 1];
__device__ int g_cursor   [N_NODES];
__device__ int g_csr_src  [N_EDGES];
__device__ int g_bsum     [256];                 // block sums for scan (196 used)

// Split bf16 feature pipeline
__device__ __nv_bfloat16 g_x_hi [(size_t)N_NODES * IN_C];
__device__ __nv_bfloat16 g_x_lo [(size_t)N_NODES * IN_C];
__device__ __nv_bfloat16 g_a1_hi[(size_t)N_NODES * IN_C];
__device__ __nv_bfloat16 g_a1_lo[(size_t)N_NODES * IN_C];
__device__ __nv_bfloat16 g_h_hi [(size_t)N_NODES * HID_C];
__device__ __nv_bfloat16 g_h_lo [(size_t)N_NODES * HID_C];

// Pre-split transposed weights: Wt[n][k] = W[k][n], bf16 hi/lo pair
__device__ __nv_bfloat16 g_wt1_hi[HID_C * (2 * IN_C)];
__device__ __nv_bfloat16 g_wt1_lo[HID_C * (2 * IN_C)];
__device__ __nv_bfloat16 g_wt2_hi[OUT_C * (2 * HID_C)];
__device__ __nv_bfloat16 g_wt2_lo[OUT_C * (2 * HID_C)];

// ---------------------------------------------------------------------------
// Helpers
// ---------------------------------------------------------------------------
__device__ __forceinline__ uint32_t smem_to_u32(const void* p) {
    uint32_t a;
    asm("{ .reg .u64 t; cvta.to.shared.u64 t, %1; cvt.u32.u64 %0, t; }" : "=r"(a) : "l"(p));
    return a;
}

#define SMEM_SWIZZLE_128B(off) ((off) ^ (((off) >> 3) & 0x70))

__device__ __forceinline__ void ldsm_x4(uint32_t* r, uint32_t addr) {
    asm volatile("ldmatrix.sync.aligned.m8n8.x4.shared.b16 {%0,%1,%2,%3}, [%4];"
        : "=r"(r[0]), "=r"(r[1]), "=r"(r[2]), "=r"(r[3]) : "r"(addr));
}

__device__ __forceinline__ void mma_bf16(float* c, const uint32_t* a, const uint32_t* b) {
    asm volatile("mma.sync.aligned.m16n8k16.row.col.f32.bf16.bf16.f32 "
        "{%0,%1,%2,%3}, {%4,%5,%6,%7}, {%8,%9}, {%0,%1,%2,%3};"
        : "+f"(c[0]), "+f"(c[1]), "+f"(c[2]), "+f"(c[3])
        : "r"(a[0]), "r"(a[1]), "r"(a[2]), "r"(a[3]), "r"(b[0]), "r"(b[1]));
}

__device__ __forceinline__ void cp_async16(uint32_t smem, const void* g, bool valid) {
    int sz = valid ? 16 : 0;
    asm volatile("cp.async.cg.shared.global [%0], [%1], 16, %2;"
        :: "r"(smem), "l"(g), "r"(sz) : "memory");
}
#define CP_COMMIT() asm volatile("cp.async.commit_group;" ::: "memory")
#define CP_WAIT(n)  asm volatile("cp.async.wait_group %0;" :: "n"(n) : "memory")
#define BAR_SYNC(id, cnt) asm volatile("bar.sync %0, %1;" :: "r"(id), "r"(cnt) : "memory")

// split one fp32 into hi/lo bf16
__device__ __forceinline__ void split_f32(float v, __nv_bfloat16& h, __nv_bfloat16& l) {
    h = __float2bfloat16_rn(v);
    l = __float2bfloat16_rn(v - __bfloat162float(h));
}

// ---------------------------------------------------------------------------
// CSR build
// ---------------------------------------------------------------------------
__global__ void zero_int_kernel(int* __restrict__ p, int n)
{
    int i = blockIdx.x * blockDim.x + threadIdx.x;
    if (i < n) p[i] = 0;
}

__global__ void hist_kernel(const int* __restrict__ dst)
{
    int e = blockIdx.x * blockDim.x + threadIdx.x;
    if (e < N_EDGES) atomicAdd(&g_cnt_int[dst[e]], 1);
}

__global__ void scan_stage1_kernel()
{
    __shared__ int sdata[256];
    int tid = threadIdx.x;
    int i = blockIdx.x * 256 + tid;
    int v = (i < N_NODES) ? g_cnt_int[i] : 0;
    sdata[tid] = v;
    __syncthreads();
    #pragma unroll
    for (int s = 1; s < 256; s <<= 1) {
        int t = (tid >= s) ? sdata[tid - s] : 0;
        __syncthreads();
        sdata[tid] += t;
        __syncthreads();
    }
    if (i < N_NODES) g_row_start[i] = sdata[tid] - v;
    if (tid == 255) g_bsum[blockIdx.x] = sdata[255];
}

__global__ void scan_stage2_kernel(int nblocks)
{
    __shared__ int sdata[256];
    int tid = threadIdx.x;
    int v = (tid < nblocks) ? g_bsum[tid] : 0;
    sdata[tid] = v;
    __syncthreads();
    #pragma unroll
    for (int s = 1; s < 256; s <<= 1) {
        int t = (tid >= s) ? sdata[tid - s] : 0;
        __syncthreads();
        sdata[tid] += t;
        __syncthreads();
    }
    if (tid < nblocks) g_bsum[tid] = sdata[tid] - v;
    if (tid == 255) g_row_start[N_NODES] = sdata[255];
}

__global__ void scan_stage3_kernel()
{
    int i = blockIdx.x * blockDim.x + threadIdx.x;
    if (i < N_NODES) {
        int rs = g_row_start[i] + g_bsum[blockIdx.x];
        g_row_start[i] = rs;
        g_cursor[i]    = rs;
    }
}

__global__ void fill_kernel(const int* __restrict__ src, const int* __restrict__ dst)
{
    int e = blockIdx.x * blockDim.x + threadIdx.x;
    if (e < N_EDGES) {
        int pos = atomicAdd(&g_cursor[dst[e]], 1);
        g_csr_src[pos] = src[e];
    }
}

// ---------------------------------------------------------------------------
// Split fp32 features -> hi/lo bf16
// ---------------------------------------------------------------------------
__global__ void split_feat_kernel(const float* __restrict__ in,
                                  __nv_bfloat16* __restrict__ hi,
                                  __nv_bfloat16* __restrict__ lo,
                                  int n4)
{
    int i = blockIdx.x * blockDim.x + threadIdx.x;
    if (i >= n4) return;
    float4 v = *(const float4*)(in + i * 4);
    __nv_bfloat16 h0, h1, h2, h3, l0, l1, l2, l3;
    split_f32(v.x, h0, l0); split_f32(v.y, h1, l1);
    split_f32(v.z, h2, l2); split_f32(v.w, h3, l3);
    __nv_bfloat162* ph = (__nv_bfloat162*)(hi + i * 4);
    __nv_bfloat162* pl = (__nv_bfloat162*)(lo + i * 4);
    ph[0] = __nv_bfloat162(h0, h1); ph[1] = __nv_bfloat162(h2, h3);
    pl[0] = __nv_bfloat162(l0, l1); pl[1] = __nv_bfloat162(l2, l3);
}

// ---------------------------------------------------------------------------
// Gather-aggregate (layer 1 only): split bf16 in, split bf16 out
// ---------------------------------------------------------------------------
template<int C>
__global__ void gather_bf16_kernel(const __nv_bfloat16* __restrict__ fhi,
                                   const __nv_bfloat16* __restrict__ flo,
                                   __nv_bfloat16* __restrict__ ahi,
                                   __nv_bfloat16* __restrict__ alo)
{
    int node = blockIdx.x * (blockDim.x >> 5) + (threadIdx.x >> 5);
    if (node >= N_NODES) return;
    int lane = threadIdx.x & 31;
    int beg = g_row_start[node];
    int end = g_row_start[node + 1];

    constexpr int V = C / 128;
    float4 acc[V];
    #pragma unroll
    for (int v = 0; v < V; v++) acc[v] = make_float4(0.f, 0.f, 0.f, 0.f);

    for (int k = beg; k < end; k++) {
        int s = g_csr_src[k];
        const uint2* ph = (const uint2*)(fhi + (size_t)s * C);
        const uint2* pl = (const uint2*)(flo + (size_t)s * C);
        #pragma unroll
        for (int v = 0; v < V; v++) {
            uint2 hw = ph[lane + 32 * v];
            uint2 lw = pl[lane + 32 * v];
            float2 h0 = __bfloat1622float2(*(__nv_bfloat162*)&hw.x);
            float2 h1 = __bfloat1622float2(*(__nv_bfloat162*)&hw.y);
            float2 l0 = __bfloat1622float2(*(__nv_bfloat162*)&lw.x);
            float2 l1 = __bfloat1622float2(*(__nv_bfloat162*)&lw.y);
            acc[v].x += h0.x + l0.x;
            acc[v].y += h0.y + l0.y;
            acc[v].z += h1.x + l1.x;
            acc[v].w += h1.y + l1.y;
        }
    }
    float inv = 1.0f / (float)max(end - beg, 1);
    #pragma unroll
    for (int v = 0; v < V; v++) {
        float4 a = acc[v];
        a.x *= inv; a.y *= inv; a.z *= inv; a.w *= inv;
        __nv_bfloat16 h0, h1, h2, h3, l0, l1, l2, l3;
        split_f32(a.x, h0, l0); split_f32(a.y, h1, l1);
        split_f32(a.z, h2, l2); split_f32(a.w, h3, l3);
        uint2 hw, lw;
        *(__nv_bfloat162*)&hw.x = __nv_bfloat162(h0, h1);
        *(__nv_bfloat162*)&hw.y = __nv_bfloat162(h2, h3);
        *(__nv_bfloat162*)&lw.x = __nv_bfloat162(l0, l1);
        *(__nv_bfloat162*)&lw.y = __nv_bfloat162(l2, l3);
        ((uint2*)(ahi + (size_t)node * C))[lane + 32 * v] = hw;
        ((uint2*)(alo + (size_t)node * C))[lane + 32 * v] = lw;
    }
}

// ---------------------------------------------------------------------------
// Weight prep: transpose [K,N]->[N,K] and split fp32 -> bf16 hi + lo
// ---------------------------------------------------------------------------
template<int K_TOT, int N_TOT>
__global__ void prep_w_kernel(const float* __restrict__ Wa,
                              const float* __restrict__ Wb,
                              __nv_bfloat16* __restrict__ hi,
                              __nv_bfloat16* __restrict__ lo)
{
    int idx = blockIdx.x * blockDim.x + threadIdx.x;
    if (idx >= N_TOT * K_TOT) return;
    int n = idx / K_TOT;
    int k = idx % K_TOT;
    constexpr int Kh = K_TOT / 2;
    float w = (k < Kh) ? Wa[(size_t)k * N_TOT + n] : Wb[(size_t)(k - Kh) * N_TOT + n];
    __nv_bfloat16 h, l;
    split_f32(w, h, l);
    hi[idx] = h;
    lo[idx] = l;
}

// ---------------------------------------------------------------------------
// Layer-1 GEMM (unchanged pipelined version), BN=64, split bf16 out.
// ---------------------------------------------------------------------------
struct __align__(128) MmaStage {
    __nv_bfloat16 a_hi[128 * 64];
    __nv_bfloat16 a_lo[128 * 64];
    __nv_bfloat16 b_hi[64 * 64];
    __nv_bfloat16 b_lo[64 * 64];
};
#define MMA_SMEM_TOTAL (2 * (int)sizeof(MmaStage))

template<int K_A, int N_TOT, bool RELU>
__global__ __launch_bounds__(256)
void sage_mma_warp(const __nv_bfloat16* __restrict__ AaggHi,
                   const __nv_bfloat16* __restrict__ AaggLo,
                   const __nv_bfloat16* __restrict__ ArootHi,
                   const __nv_bfloat16* __restrict__ ArootLo,
                   const __nv_bfloat16* __restrict__ WtHi,
                   const __nv_bfloat16* __restrict__ WtLo,
                   const float* __restrict__ bias,
                   __nv_bfloat16* __restrict__ CoutHi,
                   __nv_bfloat16* __restrict__ CoutLo,
                   int M)
{
    extern __shared__ char smem_raw[];
    MmaStage* st = (MmaStage*)smem_raw;
    constexpr int K_TOT  = 2 * K_A;
    constexpr int CHUNKS = K_TOT / 64;

    int tid  = threadIdx.x;
    int wid  = tid >> 5;
    int lane = tid & 31;
    int m0 = blockIdx.x * 128;
    int n0 = blockIdx.y * 64;

    auto load_chunk = [&](int c, int s) {
        uint32_t sa_hi = smem_to_u32(st[s].a_hi);
        uint32_t sa_lo = smem_to_u32(st[s].a_lo);
        uint32_t sb_hi = smem_to_u32(st[s].b_hi);
        uint32_t sb_lo = smem_to_u32(st[s].b_lo);
        {
            bool agg_half = (c < CHUNKS / 2);
            const __nv_bfloat16* Ah = agg_half ? AaggHi : ArootHi;
            const __nv_bfloat16* Al = agg_half ? AaggLo : ArootLo;
            int k0 = (agg_half ? c : c - CHUNKS / 2) * 64;
            int row = tid >> 1;
            int j0  = (tid & 1) * 4;
            int gm = m0 + row;
            bool valid = gm < M;
            const __nv_bfloat16* ph = Ah + (size_t)gm * K_A + k0;
            const __nv_bfloat16* pl = Al + (size_t)gm * K_A + k0;
            #pragma unroll
            for (int j = j0; j < j0 + 4; j++) {
                uint32_t off = SMEM_SWIZZLE_128B((uint32_t)(row * 128 + j * 16));
                cp_async16(sa_hi + off, ph + j * 8, valid);
                cp_async16(sa_lo + off, pl + j * 8, valid);
            }
        }
        {
            int kg = c * 64;
            int row = tid >> 2;
            int j0  = (tid & 3) * 2;
            const __nv_bfloat16* bh = WtHi + (size_t)(n0 + row) * K_TOT + kg;
            const __nv_bfloat16* bl = WtLo + (size_t)(n0 + row) * K_TOT + kg;
            #pragma unroll
            for (int j = j0; j < j0 + 2; j++) {
                uint32_t off = SMEM_SWIZZLE_128B((uint32_t)(row * 128 + j * 16));
                cp_async16(sb_hi + off, bh + j * 8, true);
                cp_async16(sb_lo + off, bl + j * 8, true);
            }
        }
        CP_COMMIT();
    };

    float acc[8][4];
    #pragma unroll
    for (int nt = 0; nt < 8; nt++)
        #pragma unroll
        for (int q = 0; q < 4; q++) acc[nt][q] = 0.f;

    load_chunk(0, 0);

    for (int c = 0; c < CHUNKS; c++) {
        int s = c & 1;
        if (c + 1 < CHUNKS) {
            load_chunk(c + 1, (c + 1) & 1);
            CP_WAIT(1);
        } else {
            CP_WAIT(0);
        }
        __syncthreads();

        uint32_t sa_hi = smem_to_u32(st[s].a_hi);
        uint32_t sa_lo = smem_to_u32(st[s].a_lo);
        uint32_t sb_hi = smem_to_u32(st[s].b_hi);
        uint32_t sb_lo = smem_to_u32(st[s].b_lo);

        #pragma unroll
        for (int ks = 0; ks < 4; ks++) {
            uint32_t ah[4], al[4];
            {
                int r  = wid * 16 + (lane & 7) + ((lane >> 3) & 1) * 8;
                int cb = ks * 32 + ((lane >> 4) & 1) * 16;
                uint32_t off = SMEM_SWIZZLE_128B((uint32_t)(r * 128 + cb));
                ldsm_x4(ah, sa_hi + off);
                ldsm_x4(al, sa_lo + off);
            }
            #pragma unroll
            for (int half = 0; half < 2; half++) {
                uint32_t bh[2][4], bl[2][4];
                #pragma unroll
                for (int q = 0; q < 2; q++) {
                    int nt0 = half * 4 + q * 2;
                    int r  = nt0 * 8 + (lane & 7) + ((lane >> 4) & 1) * 8;
                    int cb = ks * 32 + ((lane >> 3) & 1) * 16;
                    uint32_t off = SMEM_SWIZZLE_128B((uint32_t)(r * 128 + cb));
                    ldsm_x4(bh[q], sb_hi + off);
                    ldsm_x4(bl[q], sb_lo + off);
                }
                #pragma unroll
                for (int q = 0; q < 2; q++)
                    #pragma unroll
                    for (int sub = 0; sub < 2; sub++) {
                        int nt = half * 4 + q * 2 + sub;
                        mma_bf16(acc[nt], ah, &bh[q][sub * 2]);
                        mma_bf16(acc[nt], al, &bh[q][sub * 2]);
                        mma_bf16(acc[nt], ah, &bl[q][sub * 2]);
                    }
            }
        }
        __syncthreads();
    }

    int g = lane >> 2;
    int t = lane & 3;
    int r0 = m0 + wid * 16 + g;
    int r1 = r0 + 8;
    #pragma unroll
    for (int nt = 0; nt < 8; nt++) {
        int n = n0 + nt * 8 + 2 * t;
        float2 bb = *(const float2*)(bias + n);
        float c0 = acc[nt][0] + bb.x;
        float c1 = acc[nt][1] + bb.y;
        float c2 = acc[nt][2] + bb.x;
        float c3 = acc[nt][3] + bb.y;
        if (RELU) {
            c0 = fmaxf(c0, 0.f); c1 = fmaxf(c1, 0.f);
            c2 = fmaxf(c2, 0.f); c3 = fmaxf(c3, 0.f);
        }
        if (r0 < M) {
            __nv_bfloat16 h0, h1, l0, l1;
            split_f32(c0, h0, l0); split_f32(c1, h1, l1);
            *(__nv_bfloat162*)(CoutHi + (size_t)r0 * N_TOT + n) = __nv_bfloat162(h0, h1);
            *(__nv_bfloat162*)(CoutLo + (size_t)r0 * N_TOT + n) = __nv_bfloat162(l0, l1);
        }
        if (r1 < M) {
            __nv_bfloat16 h2, h3, l2, l3;
            split_f32(c2, h2, l2); split_f32(c3, h3, l3);
            *(__nv_bfloat162*)(CoutHi + (size_t)r1 * N_TOT + n) = __nv_bfloat162(h2, h3);
            *(__nv_bfloat162*)(CoutLo + (size_t)r1 * N_TOT + n) = __nv_bfloat162(l2, l3);
        }
    }
}

// ---------------------------------------------------------------------------
// Layer-2 FUSED gather + GEMM, warp-specialized.
// out[M,128] = agg2 @ W2l + h @ W2r + b2, agg2 gathered in-kernel from h.
// 384 threads: warps 0-7 = MMA consumers (m16 each, n128), warps 8-11 =
// gather producers. 8 chunk slots: 0-3 root (cp.async), 4-7 agg (produced).
// SMEM: B stages 2x32KB @0, rootA stages 2x32KB @64K, agg bufs 2x32KB @128K,
// flags @192K.  (hi at +0, lo at +16384 inside each 32KB region)
// ---------------------------------------------------------------------------
#define F2_B(s)   (smem_raw + (s) * 32768)
#define F2_RA(s)  (smem_raw + 65536 + (s) * 32768)
#define F2_AG(p)  (smem_raw + 131072 + (p) * 32768)
#define F2_FLAGS  196608
#define F2_TOTAL  (196608 + 128)

__global__ __launch_bounds__(384)
void sage_mma_fused2(const __nv_bfloat16* __restrict__ hhi,
                     const __nv_bfloat16* __restrict__ hlo,
                     const __nv_bfloat16* __restrict__ WtHi,   // [128][512]
                     const __nv_bfloat16* __restrict__ WtLo,
                     const float* __restrict__ bias,
                     float* __restrict__ out,
                     int M)
{
    extern __shared__ char smem_raw[];
    volatile int* flags = (volatile int*)(smem_raw + F2_FLAGS);  // [0]=prod, [1]=cons
    int tid  = threadIdx.x;
    int wid  = tid >> 5;
    int lane = tid & 31;
    int m0 = blockIdx.x * 128;

    if (tid < 2) flags[tid] = 0;
    __syncthreads();                 // the ONLY full-CTA barrier

    if (wid < 8) {
        // ================= CONSUMERS (256 threads) =================
        auto load_slot = [&](int c) {
            int s = c & 1;
            // B: chunk kg; root slots 0-3 -> Wt rows 256 + c*64; agg 4-7 -> (c-4)*64
            int kg = (c < 4) ? (256 + c * 64) : ((c - 4) * 64);
            {
                int row = tid >> 1;          // 0..127 (n)
                int j0  = (tid & 1) * 4;
                uint32_t sb_hi = smem_to_u32(F2_B(s));
                uint32_t sb_lo = smem_to_u32(F2_B(s) + 16384);
                const __nv_bfloat16* bh = WtHi + (size_t)row * 512 + kg;
                const __nv_bfloat16* bl = WtLo + (size_t)row * 512 + kg;
                #pragma unroll
                for (int j = j0; j < j0 + 4; j++) {
                    uint32_t off = SMEM_SWIZZLE_128B((uint32_t)(row * 128 + j * 16));
                    cp_async16(sb_hi + off, bh + j * 8, true);
                    cp_async16(sb_lo + off, bl + j * 8, true);
                }
            }
            if (c < 4) {                     // root A: h cols c*64
                int row = tid >> 1;
                int j0  = (tid & 1) * 4;
                int gm = m0 + row;
                bool valid = gm < M;
                uint32_t sa_hi = smem_to_u32(F2_RA(s));
                uint32_t sa_lo = smem_to_u32(F2_RA(s) + 16384);
                const __nv_bfloat16* ph = hhi + (size_t)gm * 256 + c * 64;
                const __nv_bfloat16* pl = hlo + (size_t)gm * 256 + c * 64;
                #pragma unroll
                for (int j = j0; j < j0 + 4; j++) {
                    uint32_t off = SMEM_SWIZZLE_128B((uint32_t)(row * 128 + j * 16));
                    cp_async16(sa_hi + off, ph + j * 8, valid);
                    cp_async16(sa_lo + off, pl + j * 8, valid);
                }
            }
            CP_COMMIT();
        };

        float acc[16][4];
        #pragma unroll
        for (int nt = 0; nt < 16; nt++)
            #pragma unroll
            for (int q = 0; q < 4; q++) acc[nt][q] = 0.f;

        load_slot(0);
        for (int c = 0; c < 8; c++) {
            int s = c & 1;
            if (c + 1 < 8) { load_slot(c + 1); CP_WAIT(1); }
            else           { CP_WAIT(0); }
            BAR_SYNC(2, 256);

            uint32_t sa_hi, sa_lo;
            if (c < 4) {
                sa_hi = smem_to_u32(F2_RA(s));
                sa_lo = smem_to_u32(F2_RA(s) + 16384);
            } else {
                int a = c - 4;
                while (flags[0] < a + 1) { }       // wait producer
                __threadfence_block();
                sa_hi = smem_to_u32(F2_AG(a & 1));
                sa_lo = smem_to_u32(F2_AG(a & 1) + 16384);
            }
            uint32_t sb_hi = smem_to_u32(F2_B(s));
            uint32_t sb_lo = smem_to_u32(F2_B(s) + 16384);

            #pragma unroll
            for (int ks = 0; ks < 4; ks++) {
                uint32_t ah[4], al[4];
                {
                    int r  = wid * 16 + (lane & 7) + ((lane >> 3) & 1) * 8;
                    int cb = ks * 32 + ((lane >> 4) & 1) * 16;
                    uint32_t off = SMEM_SWIZZLE_128B((uint32_t)(r * 128 + cb));
                    ldsm_x4(ah, sa_hi + off);
                    ldsm_x4(al, sa_lo + off);
                }
                #pragma unroll
                for (int quarter = 0; quarter < 4; quarter++) {
                    uint32_t bh[2][4], bl[2][4];
                    #pragma unroll
                    for (int q = 0; q < 2; q++) {
                        int nt0 = quarter * 4 + q * 2;
                        int r  = nt0 * 8 + (lane & 7) + ((lane >> 4) & 1) * 8;
                        int cb = ks * 32 + ((lane >> 3) & 1) * 16;
                        uint32_t off = SMEM_SWIZZLE_128B((uint32_t)(r * 128 + cb));
                        ldsm_x4(bh[q], sb_hi + off);
                        ldsm_x4(bl[q], sb_lo + off);
                    }
                    #pragma unroll
                    for (int q = 0; q < 2; q++)
                        #pragma unroll
                        for (int sub = 0; sub < 2; sub++) {
                            int nt = quarter * 4 + q * 2 + sub;
                            mma_bf16(acc[nt], ah, &bh[q][sub * 2]);
                            mma_bf16(acc[nt], al, &bh[q][sub * 2]);
                            mma_bf16(acc[nt], ah, &bl[q][sub * 2]);
                        }
                }
            }
            BAR_SYNC(2, 256);
            if (tid == 0) { __threadfence_block(); flags[1] = c + 1; }
        }

        // epilogue
        int g = lane >> 2;
        int t = lane & 3;
        int r0 = m0 + wid * 16 + g;
        int r1 = r0 + 8;
        #pragma unroll
        for (int nt = 0; nt < 16; nt++) {
            int n = nt * 8 + 2 * t;
            float2 bb = *(const float2*)(bias + n);
            float c0 = acc[nt][0] + bb.x;
            float c1 = acc[nt][1] + bb.y;
            float c2 = acc[nt][2] + bb.x;
            float c3 = acc[nt][3] + bb.y;
            if (r0 < M) *(float2*)(out + (size_t)r0 * 128 + n) = make_float2(c0, c1);
            if (r1 < M) *(float2*)(out + (size_t)r1 * 128 + n) = make_float2(c2, c3);
        }
    } else {
        // ================= PRODUCERS (128 threads, warps 8-11) =================
        int pw = wid - 8;                    // 0..3
        for (int a = 0; a < 4; a++) {
            if (a >= 2) {                    // buf reused: wait consumer slot a+2 done
                while (flags[1] < a + 3) { }
                __threadfence_block();
            }
            char* bhi = F2_AG(a & 1);
            char* blo = F2_AG(a & 1) + 16384;
            int acol = a * 64;
            for (int j = 0; j < 32; j++) {
                int r  = pw + 4 * j;         // interleaved rows for balance
                int gm = m0 + r;
                float s0 = 0.f, s1 = 0.f;
                if (gm < M) {
                    int beg = g_row_start[gm];
                    int end = g_row_start[gm + 1];
                    int k = beg;
                    for (; k + 1 < end; k += 2) {
                        int sA = g_csr_src[k];
                        int sB = g_csr_src[k + 1];
                        float2 hA = __bfloat1622float2(*(const __nv_bfloat162*)(hhi + (size_t)sA * 256 + acol + lane * 2));
                        float2 lA = __bfloat1622float2(*(const __nv_bfloat162*)(hlo + (size_t)sA * 256 + acol + lane * 2));
                        float2 hB = __bfloat1622float2(*(const __nv_bfloat162*)(hhi + (size_t)sB * 256 + acol + lane * 2));
                        float2 lB = __bfloat1622float2(*(const __nv_bfloat162*)(hlo + (size_t)sB * 256 + acol + lane * 2));
                        s0 += (hA.x + lA.x) + (hB.x + lB.x);
                        s1 += (hA.y + lA.y) + (hB.y + lB.y);
                    }
                    if (k < end) {
                        int sA = g_csr_src[k];
                        float2 hA = __bfloat1622float2(*(const __nv_bfloat162*)(hhi + (size_t)sA * 256 + acol + lane * 2));
                        float2 lA = __bfloat1622float2(*(const __nv_bfloat162*)(hlo + (size_t)sA * 256 + acol + lane * 2));
                        s0 += hA.x + lA.x;
                        s1 += hA.y + lA.y;
                    }
                    float inv = 1.0f / (float)max(end - beg, 1);
                    s0 *= inv; s1 *= inv;
                }
                __nv_bfloat16 h0, h1, l0, l1;
                split_f32(s0, h0, l0); split_f32(s1, h1, l1);
                uint32_t off = SMEM_SWIZZLE_128B((uint32_t)(r * 128 + lane * 4));
                *(__nv_bfloat162*)(bhi + off) = __nv_bfloat162(h0, h1);
                *(__nv_bfloat162*)(blo + off) = __nv_bfloat162(l0, l1);
            }
            BAR_SYNC(1, 128);                // all producers done with buf a
            if (pw == 0 && lane == 0) { __threadfence_block(); flags[0] = a + 1; }
        }
    }
}

// ---------------------------------------------------------------------------
// Launch
// ---------------------------------------------------------------------------
extern "C" void kernel_launch(void* const* d_in, const int* in_sizes, int n_in,
                              void* d_out, int out_size)
{
    const float* x   = (const float*)d_in[0];
    const int*   ei  = (const int*)d_in[1];     // int32 (JAX x64 disabled)
    const float* W1l = (const float*)d_in[2];
    const float* b1  = (const float*)d_in[3];
    const float* W1r = (const float*)d_in[4];
    const float* W2l = (const float*)d_in[5];
    const float* b2  = (const float*)d_in[6];
    const float* W2r = (const float*)d_in[7];
    float*       out = (float*)d_out;

    const int* src = ei;
    const int* dst = ei + N_EDGES;

    int* cnt_int;
    __nv_bfloat16 *xhi, *xlo, *a1hi, *a1lo, *hhi, *hlo;
    __nv_bfloat16 *wt1h, *wt1l, *wt2h, *wt2l;
    cudaGetSymbolAddress((void**)&cnt_int, g_cnt_int);
    cudaGetSymbolAddress((void**)&xhi,  g_x_hi);
    cudaGetSymbolAddress((void**)&xlo,  g_x_lo);
    cudaGetSymbolAddress((void**)&a1hi, g_a1_hi);
    cudaGetSymbolAddress((void**)&a1lo, g_a1_lo);
    cudaGetSymbolAddress((void**)&hhi,  g_h_hi);
    cudaGetSymbolAddress((void**)&hlo,  g_h_lo);
    cudaGetSymbolAddress((void**)&wt1h, g_wt1_hi);
    cudaGetSymbolAddress((void**)&wt1l, g_wt1_lo);
    cudaGetSymbolAddress((void**)&wt2h, g_wt2_hi);
    cudaGetSymbolAddress((void**)&wt2l, g_wt2_lo);

    cudaFuncSetAttribute(sage_mma_warp<IN_C, HID_C, true>,
                         cudaFuncAttributeMaxDynamicSharedMemorySize, MMA_SMEM_TOTAL);
    cudaFuncSetAttribute(sage_mma_fused2,
                         cudaFuncAttributeMaxDynamicSharedMemorySize, F2_TOTAL);

    // ---- CSR build (parallel scan) ----
    const int NB = (N_NODES + 255) / 256;
    zero_int_kernel<<<NB, 256>>>(cnt_int, N_NODES);
    hist_kernel<<<(N_EDGES + 255) / 256, 256>>>(dst);
    scan_stage1_kernel<<<NB, 256>>>();
    scan_stage2_kernel<<<1, 256>>>(NB);
    scan_stage3_kernel<<<NB, 256>>>();
    fill_kernel<<<(N_EDGES + 255) / 256, 256>>>(src, dst);

    // ---- feature + weight splits ----
    {
        int n4 = N_NODES * IN_C / 4;
        split_feat_kernel<<<(n4 + 255) / 256, 256>>>(x, xhi, xlo, n4);
    }
    prep_w_kernel<2 * IN_C,  HID_C><<<(HID_C * 2 * IN_C  + 255) / 256, 256>>>(W1l, W1r, wt1h, wt1l);
    prep_w_kernel<2 * HID_C, OUT_C><<<(OUT_C * 2 * HID_C + 255) / 256, 256>>>(W2l, W2r, wt2h, wt2l);

    int mgrid = (N_NODES + 127) / 128;

    // ---- layer 1: gather + pipelined GEMM (split bf16 out) ----
    {
        int warps_per_block = 8;
        int grid = (N_NODES + warps_per_block - 1) / warps_per_block;
        gather_bf16_kernel<IN_C><<<grid, warps_per_block * 32>>>(xhi, xlo, a1hi, a1lo);
    }
    {
        dim3 grid(mgrid, HID_C / 64);
        sage_mma_warp<IN_C, HID_C, true><<<grid, 256, MMA_SMEM_TOTAL>>>(
            a1hi, a1lo, xhi, xlo, wt1h, wt1l, b1, hhi, hlo, N_NODES);
    }

    // ---- layer 2: fused gather + GEMM ----
    sage_mma_fused2<<<mgrid, 384, F2_TOTAL>>>(hhi, hlo, wt2h, wt2l, b2, out, N_NODES);
}

// round 11
// speedup vs baseline: 2.5129x; 2.5129x over previous
#include <cuda_runtime.h>
#include <cuda_bf16.h>
#include <cstdint>

// Problem constants (match reference_code)
#define IN_C    128
#define HID_C   256
#define OUT_C   128
#define N_NODES 50000
#define N_EDGES 600000

// ---------------------------------------------------------------------------
// Scratch (no cudaMalloc allowed): device globals
// ---------------------------------------------------------------------------
__device__ int g_cnt_int  [N_NODES];
__device__ int g_row_start[N_NODES + 1];
__device__ int g_cursor   [N_NODES];
__device__ int g_csr_src  [N_EDGES];
__device__ int g_bsum     [256];                 // block sums for scan (196 used)

// Split bf16 feature pipeline
__device__ __nv_bfloat16 g_x_hi [(size_t)N_NODES * IN_C];
__device__ __nv_bfloat16 g_x_lo [(size_t)N_NODES * IN_C];
__device__ __nv_bfloat16 g_a1_hi[(size_t)N_NODES * IN_C];
__device__ __nv_bfloat16 g_a1_lo[(size_t)N_NODES * IN_C];
__device__ __nv_bfloat16 g_h_hi [(size_t)N_NODES * HID_C];
__device__ __nv_bfloat16 g_h_lo [(size_t)N_NODES * HID_C];
__device__ __nv_bfloat16 g_a2_hi[(size_t)N_NODES * HID_C];
__device__ __nv_bfloat16 g_a2_lo[(size_t)N_NODES * HID_C];

// Pre-split transposed weights: Wt[n][k] = W[k][n], bf16 hi/lo pair
__device__ __nv_bfloat16 g_wt1_hi[HID_C * (2 * IN_C)];
__device__ __nv_bfloat16 g_wt1_lo[HID_C * (2 * IN_C)];
__device__ __nv_bfloat16 g_wt2_hi[OUT_C * (2 * HID_C)];
__device__ __nv_bfloat16 g_wt2_lo[OUT_C * (2 * HID_C)];

// ---------------------------------------------------------------------------
// Helpers
// ---------------------------------------------------------------------------
__device__ __forceinline__ uint32_t smem_to_u32(const void* p) {
    uint32_t a;
    asm("{ .reg .u64 t; cvta.to.shared.u64 t, %1; cvt.u32.u64 %0, t; }" : "=r"(a) : "l"(p));
    return a;
}

#define SMEM_SWIZZLE_128B(off) ((off) ^ (((off) >> 3) & 0x70))

__device__ __forceinline__ void ldsm_x4(uint32_t* r, uint32_t addr) {
    asm volatile("ldmatrix.sync.aligned.m8n8.x4.shared.b16 {%0,%1,%2,%3}, [%4];"
        : "=r"(r[0]), "=r"(r[1]), "=r"(r[2]), "=r"(r[3]) : "r"(addr));
}

__device__ __forceinline__ void mma_bf16(float* c, const uint32_t* a, const uint32_t* b) {
    asm volatile("mma.sync.aligned.m16n8k16.row.col.f32.bf16.bf16.f32 "
        "{%0,%1,%2,%3}, {%4,%5,%6,%7}, {%8,%9}, {%0,%1,%2,%3};"
        : "+f"(c[0]), "+f"(c[1]), "+f"(c[2]), "+f"(c[3])
        : "r"(a[0]), "r"(a[1]), "r"(a[2]), "r"(a[3]), "r"(b[0]), "r"(b[1]));
}

__device__ __forceinline__ void cp_async16(uint32_t smem, const void* g, bool valid) {
    int sz = valid ? 16 : 0;
    asm volatile("cp.async.cg.shared.global [%0], [%1], 16, %2;"
        :: "r"(smem), "l"(g), "r"(sz) : "memory");
}
#define CP_COMMIT() asm volatile("cp.async.commit_group;" ::: "memory")
#define CP_WAIT(n)  asm volatile("cp.async.wait_group %0;" :: "n"(n) : "memory")

// split one fp32 into hi/lo bf16
__device__ __forceinline__ void split_f32(float v, __nv_bfloat16& h, __nv_bfloat16& l) {
    h = __float2bfloat16_rn(v);
    l = __float2bfloat16_rn(v - __bfloat162float(h));
}

// ---------------------------------------------------------------------------
// CSR build
// ---------------------------------------------------------------------------
__global__ void zero_int_kernel(int* __restrict__ p, int n)
{
    int i = blockIdx.x * blockDim.x + threadIdx.x;
    if (i < n) p[i] = 0;
}

__global__ void hist_kernel(const int* __restrict__ dst)
{
    int e = blockIdx.x * blockDim.x + threadIdx.x;
    if (e < N_EDGES) atomicAdd(&g_cnt_int[dst[e]], 1);
}

__global__ void scan_stage1_kernel()
{
    __shared__ int sdata[256];
    int tid = threadIdx.x;
    int i = blockIdx.x * 256 + tid;
    int v = (i < N_NODES) ? g_cnt_int[i] : 0;
    sdata[tid] = v;
    __syncthreads();
    #pragma unroll
    for (int s = 1; s < 256; s <<= 1) {
        int t = (tid >= s) ? sdata[tid - s] : 0;
        __syncthreads();
        sdata[tid] += t;
        __syncthreads();
    }
    if (i < N_NODES) g_row_start[i] = sdata[tid] - v;
    if (tid == 255) g_bsum[blockIdx.x] = sdata[255];
}

__global__ void scan_stage2_kernel(int nblocks)
{
    __shared__ int sdata[256];
    int tid = threadIdx.x;
    int v = (tid < nblocks) ? g_bsum[tid] : 0;
    sdata[tid] = v;
    __syncthreads();
    #pragma unroll
    for (int s = 1; s < 256; s <<= 1) {
        int t = (tid >= s) ? sdata[tid - s] : 0;
        __syncthreads();
        sdata[tid] += t;
        __syncthreads();
    }
    if (tid < nblocks) g_bsum[tid] = sdata[tid] - v;
    if (tid == 255) g_row_start[N_NODES] = sdata[255];
}

__global__ void scan_stage3_kernel()
{
    int i = blockIdx.x * blockDim.x + threadIdx.x;
    if (i < N_NODES) {
        int rs = g_row_start[i] + g_bsum[blockIdx.x];
        g_row_start[i] = rs;
        g_cursor[i]    = rs;
    }
}

__global__ void fill_kernel(const int* __restrict__ src, const int* __restrict__ dst)
{
    int e = blockIdx.x * blockDim.x + threadIdx.x;
    if (e < N_EDGES) {
        int pos = atomicAdd(&g_cursor[dst[e]], 1);
        g_csr_src[pos] = src[e];
    }
}

// ---------------------------------------------------------------------------
// Split fp32 features -> hi/lo bf16
// ---------------------------------------------------------------------------
__global__ void split_feat_kernel(const float* __restrict__ in,
                                  __nv_bfloat16* __restrict__ hi,
                                  __nv_bfloat16* __restrict__ lo,
                                  int n4)
{
    int i = blockIdx.x * blockDim.x + threadIdx.x;
    if (i >= n4) return;
    float4 v = *(const float4*)(in + i * 4);
    __nv_bfloat16 h0, h1, h2, h3, l0, l1, l2, l3;
    split_f32(v.x, h0, l0); split_f32(v.y, h1, l1);
    split_f32(v.z, h2, l2); split_f32(v.w, h3, l3);
    __nv_bfloat162* ph = (__nv_bfloat162*)(hi + i * 4);
    __nv_bfloat162* pl = (__nv_bfloat162*)(lo + i * 4);
    ph[0] = __nv_bfloat162(h0, h1); ph[1] = __nv_bfloat162(h2, h3);
    pl[0] = __nv_bfloat162(l0, l1); pl[1] = __nv_bfloat162(l2, l3);
}

// ---------------------------------------------------------------------------
// Gather-aggregate: split bf16 in, split bf16 out. One warp per node.
// ---------------------------------------------------------------------------
template<int C>
__global__ void gather_bf16_kernel(const __nv_bfloat16* __restrict__ fhi,
                                   const __nv_bfloat16* __restrict__ flo,
                                   __nv_bfloat16* __restrict__ ahi,
                                   __nv_bfloat16* __restrict__ alo)
{
    int node = blockIdx.x * (blockDim.x >> 5) + (threadIdx.x >> 5);
    if (node >= N_NODES) return;
    int lane = threadIdx.x & 31;
    int beg = g_row_start[node];
    int end = g_row_start[node + 1];

    constexpr int V = C / 128;
    float4 acc[V];
    #pragma unroll
    for (int v = 0; v < V; v++) acc[v] = make_float4(0.f, 0.f, 0.f, 0.f);

    for (int k = beg; k < end; k++) {
        int s = g_csr_src[k];
        const uint2* ph = (const uint2*)(fhi + (size_t)s * C);
        const uint2* pl = (const uint2*)(flo + (size_t)s * C);
        #pragma unroll
        for (int v = 0; v < V; v++) {
            uint2 hw = ph[lane + 32 * v];
            uint2 lw = pl[lane + 32 * v];
            float2 h0 = __bfloat1622float2(*(__nv_bfloat162*)&hw.x);
            float2 h1 = __bfloat1622float2(*(__nv_bfloat162*)&hw.y);
            float2 l0 = __bfloat1622float2(*(__nv_bfloat162*)&lw.x);
            float2 l1 = __bfloat1622float2(*(__nv_bfloat162*)&lw.y);
            acc[v].x += h0.x + l0.x;
            acc[v].y += h0.y + l0.y;
            acc[v].z += h1.x + l1.x;
            acc[v].w += h1.y + l1.y;
        }
    }
    float inv = 1.0f / (float)max(end - beg, 1);
    #pragma unroll
    for (int v = 0; v < V; v++) {
        float4 a = acc[v];
        a.x *= inv; a.y *= inv; a.z *= inv; a.w *= inv;
        __nv_bfloat16 h0, h1, h2, h3, l0, l1, l2, l3;
        split_f32(a.x, h0, l0); split_f32(a.y, h1, l1);
        split_f32(a.z, h2, l2); split_f32(a.w, h3, l3);
        uint2 hw, lw;
        *(__nv_bfloat162*)&hw.x = __nv_bfloat162(h0, h1);
        *(__nv_bfloat162*)&hw.y = __nv_bfloat162(h2, h3);
        *(__nv_bfloat162*)&lw.x = __nv_bfloat162(l0, l1);
        *(__nv_bfloat162*)&lw.y = __nv_bfloat162(l2, l3);
        ((uint2*)(ahi + (size_t)node * C))[lane + 32 * v] = hw;
        ((uint2*)(alo + (size_t)node * C))[lane + 32 * v] = lw;
    }
}

// ---------------------------------------------------------------------------
// Weight prep: transpose [K,N]->[N,K] and split fp32 -> bf16 hi + lo
// ---------------------------------------------------------------------------
template<int K_TOT, int N_TOT>
__global__ void prep_w_kernel(const float* __restrict__ Wa,
                              const float* __restrict__ Wb,
                              __nv_bfloat16* __restrict__ hi,
                              __nv_bfloat16* __restrict__ lo)
{
    int idx = blockIdx.x * blockDim.x + threadIdx.x;
    if (idx >= N_TOT * K_TOT) return;
    int n = idx / K_TOT;
    int k = idx % K_TOT;
    constexpr int Kh = K_TOT / 2;
    float w = (k < Kh) ? Wa[(size_t)k * N_TOT + n] : Wb[(size_t)(k - Kh) * N_TOT + n];
    __nv_bfloat16 h, l;
    split_f32(w, h, l);
    hi[idx] = h;
    lo[idx] = l;
}

// ---------------------------------------------------------------------------
// Pipelined warp-MMA GEMM (generalized).
//   HALVES=2: A = [A0 | A1] (each K_TOT/2 wide)     (layer-1 full GEMM)
//   HALVES=1: A = A0 (K_TOT wide)                   (layer-2 root / agg parts)
// B rows have stride W_STRIDE; caller pre-offsets WtHi/WtLo to the base col.
// BIAS: add bias in epilogue.  ACCUM: out += result (reads existing out).
// 3-term bf16 split math, fp32 accumulators, CTA 128x64, 8 warps, 2 stages.
// ---------------------------------------------------------------------------
struct __align__(128) MmaStage {
    __nv_bfloat16 a_hi[128 * 64];
    __nv_bfloat16 a_lo[128 * 64];
    __nv_bfloat16 b_hi[64 * 64];
    __nv_bfloat16 b_lo[64 * 64];
};
#define MMA_SMEM_TOTAL (2 * (int)sizeof(MmaStage))

template<int K_TOT, int HALVES, int N_TOT, int W_STRIDE,
         bool RELU, bool SPLIT_OUT, bool BIAS, bool ACCUM>
__global__ __launch_bounds__(256)
void sage_mma_warp(const __nv_bfloat16* __restrict__ A0Hi,
                   const __nv_bfloat16* __restrict__ A0Lo,
                   const __nv_bfloat16* __restrict__ A1Hi,
                   const __nv_bfloat16* __restrict__ A1Lo,
                   const __nv_bfloat16* __restrict__ WtHi,
                   const __nv_bfloat16* __restrict__ WtLo,
                   const float* __restrict__ bias,
                   float* __restrict__ Cout,
                   __nv_bfloat16* __restrict__ CoutHi,
                   __nv_bfloat16* __restrict__ CoutLo,
                   int M)
{
    extern __shared__ char smem_raw[];
    MmaStage* st = (MmaStage*)smem_raw;
    constexpr int CHUNKS = K_TOT / 64;
    constexpr int K_SRC  = K_TOT / HALVES;

    int tid  = threadIdx.x;
    int wid  = tid >> 5;
    int lane = tid & 31;
    int m0 = blockIdx.x * 128;
    int n0 = blockIdx.y * 64;

    auto load_chunk = [&](int c, int s) {
        uint32_t sa_hi = smem_to_u32(st[s].a_hi);
        uint32_t sa_lo = smem_to_u32(st[s].a_lo);
        uint32_t sb_hi = smem_to_u32(st[s].b_hi);
        uint32_t sb_lo = smem_to_u32(st[s].b_lo);
        {
            bool first_src = (HALVES == 1) || (c < CHUNKS / 2);
            const __nv_bfloat16* Ah = first_src ? A0Hi : A1Hi;
            const __nv_bfloat16* Al = first_src ? A0Lo : A1Lo;
            int k0 = (first_src ? c : c - CHUNKS / 2) * 64;
            int row = tid >> 1;
            int j0  = (tid & 1) * 4;
            int gm = m0 + row;
            bool valid = gm < M;
            const __nv_bfloat16* ph = Ah + (size_t)gm * K_SRC + k0;
            const __nv_bfloat16* pl = Al + (size_t)gm * K_SRC + k0;
            #pragma unroll
            for (int j = j0; j < j0 + 4; j++) {
                uint32_t off = SMEM_SWIZZLE_128B((uint32_t)(row * 128 + j * 16));
                cp_async16(sa_hi + off, ph + j * 8, valid);
                cp_async16(sa_lo + off, pl + j * 8, valid);
            }
        }
        {
            int kg = c * 64;
            int row = tid >> 2;
            int j0  = (tid & 3) * 2;
            const __nv_bfloat16* bh = WtHi + (size_t)(n0 + row) * W_STRIDE + kg;
            const __nv_bfloat16* bl = WtLo + (size_t)(n0 + row) * W_STRIDE + kg;
            #pragma unroll
            for (int j = j0; j < j0 + 2; j++) {
                uint32_t off = SMEM_SWIZZLE_128B((uint32_t)(row * 128 + j * 16));
                cp_async16(sb_hi + off, bh + j * 8, true);
                cp_async16(sb_lo + off, bl + j * 8, true);
            }
        }
        CP_COMMIT();
    };

    float acc[8][4];
    #pragma unroll
    for (int nt = 0; nt < 8; nt++)
        #pragma unroll
        for (int q = 0; q < 4; q++) acc[nt][q] = 0.f;

    load_chunk(0, 0);

    for (int c = 0; c < CHUNKS; c++) {
        int s = c & 1;
        if (c + 1 < CHUNKS) {
            load_chunk(c + 1, (c + 1) & 1);
            CP_WAIT(1);
        } else {
            CP_WAIT(0);
        }
        __syncthreads();

        uint32_t sa_hi = smem_to_u32(st[s].a_hi);
        uint32_t sa_lo = smem_to_u32(st[s].a_lo);
        uint32_t sb_hi = smem_to_u32(st[s].b_hi);
        uint32_t sb_lo = smem_to_u32(st[s].b_lo);

        #pragma unroll
        for (int ks = 0; ks < 4; ks++) {
            uint32_t ah[4], al[4];
            {
                int r  = wid * 16 + (lane & 7) + ((lane >> 3) & 1) * 8;
                int cb = ks * 32 + ((lane >> 4) & 1) * 16;
                uint32_t off = SMEM_SWIZZLE_128B((uint32_t)(r * 128 + cb));
                ldsm_x4(ah, sa_hi + off);
                ldsm_x4(al, sa_lo + off);
            }
            #pragma unroll
            for (int half = 0; half < 2; half++) {
                uint32_t bh[2][4], bl[2][4];
                #pragma unroll
                for (int q = 0; q < 2; q++) {
                    int nt0 = half * 4 + q * 2;
                    int r  = nt0 * 8 + (lane & 7) + ((lane >> 4) & 1) * 8;
                    int cb = ks * 32 + ((lane >> 3) & 1) * 16;
                    uint32_t off = SMEM_SWIZZLE_128B((uint32_t)(r * 128 + cb));
                    ldsm_x4(bh[q], sb_hi + off);
                    ldsm_x4(bl[q], sb_lo + off);
                }
                #pragma unroll
                for (int q = 0; q < 2; q++)
                    #pragma unroll
                    for (int sub = 0; sub < 2; sub++) {
                        int nt = half * 4 + q * 2 + sub;
                        mma_bf16(acc[nt], ah, &bh[q][sub * 2]);
                        mma_bf16(acc[nt], al, &bh[q][sub * 2]);
                        mma_bf16(acc[nt], ah, &bl[q][sub * 2]);
                    }
            }
        }
        __syncthreads();
    }

    int g = lane >> 2;
    int t = lane & 3;
    int r0 = m0 + wid * 16 + g;
    int r1 = r0 + 8;
    #pragma unroll
    for (int nt = 0; nt < 8; nt++) {
        int n = n0 + nt * 8 + 2 * t;
        float bx = 0.f, by = 0.f;
        if (BIAS) { float2 bb = *(const float2*)(bias + n); bx = bb.x; by = bb.y; }
        float c0 = acc[nt][0] + bx;
        float c1 = acc[nt][1] + by;
        float c2 = acc[nt][2] + bx;
        float c3 = acc[nt][3] + by;
        if (RELU) {
            c0 = fmaxf(c0, 0.f); c1 = fmaxf(c1, 0.f);
            c2 = fmaxf(c2, 0.f); c3 = fmaxf(c3, 0.f);
        }
        if (SPLIT_OUT) {
            if (r0 < M) {
                __nv_bfloat16 h0, h1, l0, l1;
                split_f32(c0, h0, l0); split_f32(c1, h1, l1);
                *(__nv_bfloat162*)(CoutHi + (size_t)r0 * N_TOT + n) = __nv_bfloat162(h0, h1);
                *(__nv_bfloat162*)(CoutLo + (size_t)r0 * N_TOT + n) = __nv_bfloat162(l0, l1);
            }
            if (r1 < M) {
                __nv_bfloat16 h2, h3, l2, l3;
                split_f32(c2, h2, l2); split_f32(c3, h3, l3);
                *(__nv_bfloat162*)(CoutHi + (size_t)r1 * N_TOT + n) = __nv_bfloat162(h2, h3);
                *(__nv_bfloat162*)(CoutLo + (size_t)r1 * N_TOT + n) = __nv_bfloat162(l2, l3);
            }
        } else {
            if (r0 < M) {
                if (ACCUM) {
                    float2 p = *(float2*)(Cout + (size_t)r0 * N_TOT + n);
                    c0 += p.x; c1 += p.y;
                }
                *(float2*)(Cout + (size_t)r0 * N_TOT + n) = make_float2(c0, c1);
            }
            if (r1 < M) {
                if (ACCUM) {
                    float2 p = *(float2*)(Cout + (size_t)r1 * N_TOT + n);
                    c2 += p.x; c3 += p.y;
                }
                *(float2*)(Cout + (size_t)r1 * N_TOT + n) = make_float2(c2, c3);
            }
        }
    }
}

// ---------------------------------------------------------------------------
// Side stream + events (created at module load, BEFORE harness checkpoints;
// streams/events are not device-memory allocations)
// ---------------------------------------------------------------------------
struct StreamInit {
    cudaStream_t s2;
    cudaEvent_t  e0, e1, e2, e3;
    StreamInit() {
        cudaStreamCreateWithFlags(&s2, cudaStreamNonBlocking);
        cudaEventCreateWithFlags(&e0, cudaEventDisableTiming);
        cudaEventCreateWithFlags(&e1, cudaEventDisableTiming);
        cudaEventCreateWithFlags(&e2, cudaEventDisableTiming);
        cudaEventCreateWithFlags(&e3, cudaEventDisableTiming);
    }
};
static StreamInit g_si;

// ---------------------------------------------------------------------------
// Launch
// ---------------------------------------------------------------------------
extern "C" void kernel_launch(void* const* d_in, const int* in_sizes, int n_in,
                              void* d_out, int out_size)
{
    const float* x   = (const float*)d_in[0];
    const int*   ei  = (const int*)d_in[1];     // int32 (JAX x64 disabled)
    const float* W1l = (const float*)d_in[2];
    const float* b1  = (const float*)d_in[3];
    const float* W1r = (const float*)d_in[4];
    const float* W2l = (const float*)d_in[5];
    const float* b2  = (const float*)d_in[6];
    const float* W2r = (const float*)d_in[7];
    float*       out = (float*)d_out;

    const int* src = ei;
    const int* dst = ei + N_EDGES;

    int* cnt_int;
    __nv_bfloat16 *xhi, *xlo, *a1hi, *a1lo, *hhi, *hlo, *a2hi, *a2lo;
    __nv_bfloat16 *wt1h, *wt1l, *wt2h, *wt2l;
    cudaGetSymbolAddress((void**)&cnt_int, g_cnt_int);
    cudaGetSymbolAddress((void**)&xhi,  g_x_hi);
    cudaGetSymbolAddress((void**)&xlo,  g_x_lo);
    cudaGetSymbolAddress((void**)&a1hi, g_a1_hi);
    cudaGetSymbolAddress((void**)&a1lo, g_a1_lo);
    cudaGetSymbolAddress((void**)&hhi,  g_h_hi);
    cudaGetSymbolAddress((void**)&hlo,  g_h_lo);
    cudaGetSymbolAddress((void**)&a2hi, g_a2_hi);
    cudaGetSymbolAddress((void**)&a2lo, g_a2_lo);
    cudaGetSymbolAddress((void**)&wt1h, g_wt1_hi);
    cudaGetSymbolAddress((void**)&wt1l, g_wt1_lo);
    cudaGetSymbolAddress((void**)&wt2h, g_wt2_hi);
    cudaGetSymbolAddress((void**)&wt2l, g_wt2_lo);

    // GEMM instantiations (96KB dynamic SMEM each)
    auto gemm1 = sage_mma_warp<256, 2, HID_C, 256, true,  true,  true,  false>;
    auto gemm2r = sage_mma_warp<256, 1, OUT_C, 512, false, false, true,  false>;
    auto gemm2a = sage_mma_warp<256, 1, OUT_C, 512, false, false, false, true>;
    cudaFuncSetAttribute(gemm1,  cudaFuncAttributeMaxDynamicSharedMemorySize, MMA_SMEM_TOTAL);
    cudaFuncSetAttribute(gemm2r, cudaFuncAttributeMaxDynamicSharedMemorySize, MMA_SMEM_TOTAL);
    cudaFuncSetAttribute(gemm2a, cudaFuncAttributeMaxDynamicSharedMemorySize, MMA_SMEM_TOTAL);

    const int NB = (N_NODES + 255) / 256;
    int mgrid = (N_NODES + 127) / 128;

    // ---- fork: splits (side stream) || CSR build (main stream) ----
    cudaEventRecord(g_si.e0, 0);
    cudaStreamWaitEvent(g_si.s2, g_si.e0, 0);
    {
        int n4 = N_NODES * IN_C / 4;
        split_feat_kernel<<<(n4 + 255) / 256, 256, 0, g_si.s2>>>(x, xhi, xlo, n4);
        prep_w_kernel<2 * IN_C,  HID_C><<<(HID_C * 2 * IN_C  + 255) / 256, 256, 0, g_si.s2>>>(W1l, W1r, wt1h, wt1l);
        prep_w_kernel<2 * HID_C, OUT_C><<<(OUT_C * 2 * HID_C + 255) / 256, 256, 0, g_si.s2>>>(W2l, W2r, wt2h, wt2l);
    }
    cudaEventRecord(g_si.e1, g_si.s2);

    zero_int_kernel<<<NB, 256>>>(cnt_int, N_NODES);
    hist_kernel<<<(N_EDGES + 255) / 256, 256>>>(dst);
    scan_stage1_kernel<<<NB, 256>>>();
    scan_stage2_kernel<<<1, 256>>>(NB);
    scan_stage3_kernel<<<NB, 256>>>();
    fill_kernel<<<(N_EDGES + 255) / 256, 256>>>(src, dst);

    // ---- join: gather1 needs CSR + split_feat; GEMM1 needs wt1 ----
    cudaStreamWaitEvent(0, g_si.e1, 0);
    {
        int warps_per_block = 8;
        int grid = (N_NODES + warps_per_block - 1) / warps_per_block;
        gather_bf16_kernel<IN_C><<<grid, warps_per_block * 32>>>(xhi, xlo, a1hi, a1lo);
    }
    {
        dim3 grid(mgrid, HID_C / 64);
        gemm1<<<grid, 256, MMA_SMEM_TOTAL>>>(
            a1hi, a1lo, xhi, xlo, wt1h, wt1l, b1, nullptr, hhi, hlo, N_NODES);
    }

    // ---- fork: layer-2 root GEMM (side stream) || gather2 (main) ----
    cudaEventRecord(g_si.e2, 0);
    cudaStreamWaitEvent(g_si.s2, g_si.e2, 0);
    {
        dim3 grid(mgrid, OUT_C / 64);
        gemm2r<<<grid, 256, MMA_SMEM_TOTAL, g_si.s2>>>(
            hhi, hlo, nullptr, nullptr, wt2h + 256, wt2l + 256, b2,
            out, nullptr, nullptr, N_NODES);
    }
    cudaEventRecord(g_si.e3, g_si.s2);

    {
        int warps_per_block = 8;
        int grid = (N_NODES + warps_per_block - 1) / warps_per_block;
        gather_bf16_kernel<HID_C><<<grid, warps_per_block * 32>>>(hhi, hlo, a2hi, a2lo);
    }

    // ---- join: agg GEMM accumulates into out ----
    cudaStreamWaitEvent(0, g_si.e3, 0);
    {
        dim3 grid(mgrid, OUT_C / 64);
        gemm2a<<<grid, 256, MMA_SMEM_TOTAL>>>(
            a2hi, a2lo, nullptr, nullptr, wt2h, wt2l, nullptr,
            out, nullptr, nullptr, N_NODES);
    }
}

// round 12
// speedup vs baseline: 2.6476x; 1.0536x over previous
#include <cuda_runtime.h>
#include <cuda_bf16.h>
#include <cstdint>

// Problem constants (match reference_code)
#define IN_C    128
#define HID_C   256
#define OUT_C   128
#define N_NODES 50000
#define N_EDGES 600000

// ---------------------------------------------------------------------------
// Scratch (no cudaMalloc allowed): device globals
// ---------------------------------------------------------------------------
__device__ int g_cnt_int  [N_NODES];
__device__ int g_row_start[N_NODES + 1];
__device__ int g_cursor   [N_NODES];
__device__ int g_csr_src  [N_EDGES];
__device__ int g_bsum     [256];

// Split bf16 feature pipeline
__device__ __nv_bfloat16 g_x_hi [(size_t)N_NODES * IN_C];
__device__ __nv_bfloat16 g_x_lo [(size_t)N_NODES * IN_C];
__device__ __nv_bfloat16 g_a1_hi[(size_t)N_NODES * IN_C];
__device__ __nv_bfloat16 g_a1_lo[(size_t)N_NODES * IN_C];
__device__ __nv_bfloat16 g_h_hi [(size_t)N_NODES * HID_C];
__device__ __nv_bfloat16 g_h_lo [(size_t)N_NODES * HID_C];
__device__ float         g_y2l  [(size_t)N_NODES * OUT_C];   // h @ W2l (fp32)

// Pre-split transposed weights (bf16 hi/lo):
//  wt1[n][k], n in [0,256), k in [0,256): k<128 -> W1l[k][n], else W1r[k-128][n]
//  wt2[n][k], n in [0,256), k in [0,256): n<128 -> W2l[k][n], else W2r[k][n-128]
__device__ __nv_bfloat16 g_wt1_hi[HID_C * (2 * IN_C)];
__device__ __nv_bfloat16 g_wt1_lo[HID_C * (2 * IN_C)];
__device__ __nv_bfloat16 g_wt2_hi[(2 * OUT_C) * HID_C];
__device__ __nv_bfloat16 g_wt2_lo[(2 * OUT_C) * HID_C];

// ---------------------------------------------------------------------------
// Helpers
// ---------------------------------------------------------------------------
__device__ __forceinline__ uint32_t smem_to_u32(const void* p) {
    uint32_t a;
    asm("{ .reg .u64 t; cvta.to.shared.u64 t, %1; cvt.u32.u64 %0, t; }" : "=r"(a) : "l"(p));
    return a;
}

#define SMEM_SWIZZLE_128B(off) ((off) ^ (((off) >> 3) & 0x70))

__device__ __forceinline__ void ldsm_x4(uint32_t* r, uint32_t addr) {
    asm volatile("ldmatrix.sync.aligned.m8n8.x4.shared.b16 {%0,%1,%2,%3}, [%4];"
        : "=r"(r[0]), "=r"(r[1]), "=r"(r[2]), "=r"(r[3]) : "r"(addr));
}

__device__ __forceinline__ void mma_bf16(float* c, const uint32_t* a, const uint32_t* b) {
    asm volatile("mma.sync.aligned.m16n8k16.row.col.f32.bf16.bf16.f32 "
        "{%0,%1,%2,%3}, {%4,%5,%6,%7}, {%8,%9}, {%0,%1,%2,%3};"
        : "+f"(c[0]), "+f"(c[1]), "+f"(c[2]), "+f"(c[3])
        : "r"(a[0]), "r"(a[1]), "r"(a[2]), "r"(a[3]), "r"(b[0]), "r"(b[1]));
}

__device__ __forceinline__ void cp_async16(uint32_t smem, const void* g, bool valid) {
    int sz = valid ? 16 : 0;
    asm volatile("cp.async.cg.shared.global [%0], [%1], 16, %2;"
        :: "r"(smem), "l"(g), "r"(sz) : "memory");
}
#define CP_COMMIT() asm volatile("cp.async.commit_group;" ::: "memory")
#define CP_WAIT(n)  asm volatile("cp.async.wait_group %0;" :: "n"(n) : "memory")

__device__ __forceinline__ void split_f32(float v, __nv_bfloat16& h, __nv_bfloat16& l) {
    h = __float2bfloat16_rn(v);
    l = __float2bfloat16_rn(v - __bfloat162float(h));
}

// ---------------------------------------------------------------------------
// CSR build
// ---------------------------------------------------------------------------
__global__ void zero_int_kernel(int* __restrict__ p, int n)
{
    int i = blockIdx.x * blockDim.x + threadIdx.x;
    if (i < n) p[i] = 0;
}

__global__ void hist_kernel(const int* __restrict__ dst)
{
    int e = blockIdx.x * blockDim.x + threadIdx.x;
    if (e < N_EDGES) atomicAdd(&g_cnt_int[dst[e]], 1);
}

__global__ void scan_stage1_kernel()
{
    __shared__ int sdata[256];
    int tid = threadIdx.x;
    int i = blockIdx.x * 256 + tid;
    int v = (i < N_NODES) ? g_cnt_int[i] : 0;
    sdata[tid] = v;
    __syncthreads();
    #pragma unroll
    for (int s = 1; s < 256; s <<= 1) {
        int t = (tid >= s) ? sdata[tid - s] : 0;
        __syncthreads();
        sdata[tid] += t;
        __syncthreads();
    }
    if (i < N_NODES) g_row_start[i] = sdata[tid] - v;
    if (tid == 255) g_bsum[blockIdx.x] = sdata[255];
}

__global__ void scan_stage2_kernel(int nblocks)
{
    __shared__ int sdata[256];
    int tid = threadIdx.x;
    int v = (tid < nblocks) ? g_bsum[tid] : 0;
    sdata[tid] = v;
    __syncthreads();
    #pragma unroll
    for (int s = 1; s < 256; s <<= 1) {
        int t = (tid >= s) ? sdata[tid - s] : 0;
        __syncthreads();
        sdata[tid] += t;
        __syncthreads();
    }
    if (tid < nblocks) g_bsum[tid] = sdata[tid] - v;
    if (tid == 255) g_row_start[N_NODES] = sdata[255];
}

__global__ void scan_stage3_kernel()
{
    int i = blockIdx.x * blockDim.x + threadIdx.x;
    if (i < N_NODES) {
        int rs = g_row_start[i] + g_bsum[blockIdx.x];
        g_row_start[i] = rs;
        g_cursor[i]    = rs;
    }
}

__global__ void fill_kernel(const int* __restrict__ src, const int* __restrict__ dst)
{
    int e = blockIdx.x * blockDim.x + threadIdx.x;
    if (e < N_EDGES) {
        int pos = atomicAdd(&g_cursor[dst[e]], 1);
        g_csr_src[pos] = src[e];
    }
}

// ---------------------------------------------------------------------------
// Split fp32 features -> hi/lo bf16
// ---------------------------------------------------------------------------
__global__ void split_feat_kernel(const float* __restrict__ in,
                                  __nv_bfloat16* __restrict__ hi,
                                  __nv_bfloat16* __restrict__ lo,
                                  int n4)
{
    int i = blockIdx.x * blockDim.x + threadIdx.x;
    if (i >= n4) return;
    float4 v = *(const float4*)(in + i * 4);
    __nv_bfloat16 h0, h1, h2, h3, l0, l1, l2, l3;
    split_f32(v.x, h0, l0); split_f32(v.y, h1, l1);
    split_f32(v.z, h2, l2); split_f32(v.w, h3, l3);
    __nv_bfloat162* ph = (__nv_bfloat162*)(hi + i * 4);
    __nv_bfloat162* pl = (__nv_bfloat162*)(lo + i * 4);
    ph[0] = __nv_bfloat162(h0, h1); ph[1] = __nv_bfloat162(h2, h3);
    pl[0] = __nv_bfloat162(l0, l1); pl[1] = __nv_bfloat162(l2, l3);
}

// ---------------------------------------------------------------------------
// Gather-aggregate (layer 1): split bf16 in -> split bf16 mean out
// ---------------------------------------------------------------------------
template<int C>
__global__ void gather_bf16_kernel(const __nv_bfloat16* __restrict__ fhi,
                                   const __nv_bfloat16* __restrict__ flo,
                                   __nv_bfloat16* __restrict__ ahi,
                                   __nv_bfloat16* __restrict__ alo)
{
    int node = blockIdx.x * (blockDim.x >> 5) + (threadIdx.x >> 5);
    if (node >= N_NODES) return;
    int lane = threadIdx.x & 31;
    int beg = g_row_start[node];
    int end = g_row_start[node + 1];

    constexpr int V = C / 128;
    float4 acc[V];
    #pragma unroll
    for (int v = 0; v < V; v++) acc[v] = make_float4(0.f, 0.f, 0.f, 0.f);

    for (int k = beg; k < end; k++) {
        int s = g_csr_src[k];
        const uint2* ph = (const uint2*)(fhi + (size_t)s * C);
        const uint2* pl = (const uint2*)(flo + (size_t)s * C);
        #pragma unroll
        for (int v = 0; v < V; v++) {
            uint2 hw = ph[lane + 32 * v];
            uint2 lw = pl[lane + 32 * v];
            float2 h0 = __bfloat1622float2(*(__nv_bfloat162*)&hw.x);
            float2 h1 = __bfloat1622float2(*(__nv_bfloat162*)&hw.y);
            float2 l0 = __bfloat1622float2(*(__nv_bfloat162*)&lw.x);
            float2 l1 = __bfloat1622float2(*(__nv_bfloat162*)&lw.y);
            acc[v].x += h0.x + l0.x;
            acc[v].y += h0.y + l0.y;
            acc[v].z += h1.x + l1.x;
            acc[v].w += h1.y + l1.y;
        }
    }
    float inv = 1.0f / (float)max(end - beg, 1);
    #pragma unroll
    for (int v = 0; v < V; v++) {
        float4 a = acc[v];
        a.x *= inv; a.y *= inv; a.z *= inv; a.w *= inv;
        __nv_bfloat16 h0, h1, h2, h3, l0, l1, l2, l3;
        split_f32(a.x, h0, l0); split_f32(a.y, h1, l1);
        split_f32(a.z, h2, l2); split_f32(a.w, h3, l3);
        uint2 hw, lw;
        *(__nv_bfloat162*)&hw.x = __nv_bfloat162(h0, h1);
        *(__nv_bfloat162*)&hw.y = __nv_bfloat162(h2, h3);
        *(__nv_bfloat162*)&lw.x = __nv_bfloat162(l0, l1);
        *(__nv_bfloat162*)&lw.y = __nv_bfloat162(l2, l3);
        ((uint2*)(ahi + (size_t)node * C))[lane + 32 * v] = hw;
        ((uint2*)(alo + (size_t)node * C))[lane + 32 * v] = lw;
    }
}

// ---------------------------------------------------------------------------
// Layer-2 gather (commuted): out[node] += mean over in-edges of y2l[src]
// y2l is fp32, 128 cols. One warp per node, lane = one float4.
// ---------------------------------------------------------------------------
__global__ void gather_acc_kernel(const float* __restrict__ y2l,
                                  float* __restrict__ out)
{
    int node = blockIdx.x * (blockDim.x >> 5) + (threadIdx.x >> 5);
    if (node >= N_NODES) return;
    int lane = threadIdx.x & 31;
    int beg = g_row_start[node];
    int end = g_row_start[node + 1];

    float4 acc = make_float4(0.f, 0.f, 0.f, 0.f);
    for (int k = beg; k < end; k++) {
        int s = g_csr_src[k];
        float4 v = ((const float4*)(y2l + (size_t)s * OUT_C))[lane];
        acc.x += v.x; acc.y += v.y; acc.z += v.z; acc.w += v.w;
    }
    float inv = 1.0f / (float)max(end - beg, 1);
    float4* o = (float4*)(out + (size_t)node * OUT_C) + lane;
    float4 p = *o;
    p.x += acc.x * inv; p.y += acc.y * inv;
    p.z += acc.z * inv; p.w += acc.w * inv;
    *o = p;
}

// ---------------------------------------------------------------------------
// Weight prep
// ---------------------------------------------------------------------------
__global__ void prep_w1_kernel(const float* __restrict__ W1l,
                               const float* __restrict__ W1r,
                               __nv_bfloat16* __restrict__ hi,
                               __nv_bfloat16* __restrict__ lo)
{
    int idx = blockIdx.x * blockDim.x + threadIdx.x;
    if (idx >= HID_C * 256) return;
    int n = idx / 256;
    int k = idx % 256;
    float w = (k < 128) ? W1l[(size_t)k * HID_C + n] : W1r[(size_t)(k - 128) * HID_C + n];
    __nv_bfloat16 h, l;
    split_f32(w, h, l);
    hi[idx] = h;
    lo[idx] = l;
}

__global__ void prep_w2_kernel(const float* __restrict__ W2l,
                               const float* __restrict__ W2r,
                               __nv_bfloat16* __restrict__ hi,
                               __nv_bfloat16* __restrict__ lo)
{
    int idx = blockIdx.x * blockDim.x + threadIdx.x;
    if (idx >= 256 * HID_C) return;
    int n = idx / HID_C;          // 0..255 output col (0-127 y2l, 128-255 y2r)
    int k = idx % HID_C;          // 0..255
    float w = (n < 128) ? W2l[(size_t)k * OUT_C + n] : W2r[(size_t)k * OUT_C + (n - 128)];
    __nv_bfloat16 h, l;
    split_f32(w, h, l);
    hi[idx] = h;
    lo[idx] = l;
}

// ---------------------------------------------------------------------------
// Pipelined warp-MMA GEMM, CTA tile 128(M) x 128(N), 8 warps, 2 stages.
// 3-term bf16 split (hi*hi + lo*hi + hi*lo), fp32 accumulators.
// K_TOT in chunks of 64. HALVES=2: A=[A0|A1]; HALVES=1: A=A0.
// MODE 0 (layer1): h-out = relu(acc + bias) -> split bf16 (N_TOT stride).
// MODE 1 (layer2): blockIdx.y==0 -> y2l fp32 (no bias);
//                  blockIdx.y==1 -> out fp32 = acc + bias.
// SMEM per stage: Ahi 16K | Alo 16K | Bhi 16K | Blo 16K = 64KB; x2 stages.
// ---------------------------------------------------------------------------
#define ST_A_HI(s) (smem_raw + (s) * 65536)
#define ST_A_LO(s) (smem_raw + (s) * 65536 + 16384)
#define ST_B_HI(s) (smem_raw + (s) * 65536 + 32768)
#define ST_B_LO(s) (smem_raw + (s) * 65536 + 49152)
#define MMA_SMEM_TOTAL 131072

template<int K_TOT, int HALVES, int N_TOT, int MODE>
__global__ __launch_bounds__(256)
void sage_mma_warp(const __nv_bfloat16* __restrict__ A0Hi,
                   const __nv_bfloat16* __restrict__ A0Lo,
                   const __nv_bfloat16* __restrict__ A1Hi,
                   const __nv_bfloat16* __restrict__ A1Lo,
                   const __nv_bfloat16* __restrict__ WtHi,
                   const __nv_bfloat16* __restrict__ WtLo,
                   const float* __restrict__ bias,
                   float* __restrict__ OutF,      // MODE1: y2l base (by=0) handled below
                   float* __restrict__ OutF2,     // MODE1: out base (by=1)
                   __nv_bfloat16* __restrict__ CoutHi,
                   __nv_bfloat16* __restrict__ CoutLo,
                   int M)
{
    extern __shared__ char smem_raw[];
    constexpr int CHUNKS = K_TOT / 64;
    constexpr int K_SRC  = K_TOT / HALVES;

    int tid  = threadIdx.x;
    int wid  = tid >> 5;
    int lane = tid & 31;
    int m0 = blockIdx.x * 128;
    int n0 = blockIdx.y * 128;

    auto load_chunk = [&](int c, int s) {
        uint32_t sa_hi = smem_to_u32(ST_A_HI(s));
        uint32_t sa_lo = smem_to_u32(ST_A_LO(s));
        uint32_t sb_hi = smem_to_u32(ST_B_HI(s));
        uint32_t sb_lo = smem_to_u32(ST_B_LO(s));
        int row = tid >> 1;
        int j0  = (tid & 1) * 4;
        {
            bool first_src = (HALVES == 1) || (c < CHUNKS / 2);
            const __nv_bfloat16* Ah = first_src ? A0Hi : A1Hi;
            const __nv_bfloat16* Al = first_src ? A0Lo : A1Lo;
            int k0 = (first_src ? c : c - CHUNKS / 2) * 64;
            int gm = m0 + row;
            bool valid = gm < M;
            const __nv_bfloat16* ph = Ah + (size_t)gm * K_SRC + k0;
            const __nv_bfloat16* pl = Al + (size_t)gm * K_SRC + k0;
            #pragma unroll
            for (int j = j0; j < j0 + 4; j++) {
                uint32_t off = SMEM_SWIZZLE_128B((uint32_t)(row * 128 + j * 16));
                cp_async16(sa_hi + off, ph + j * 8, valid);
                cp_async16(sa_lo + off, pl + j * 8, valid);
            }
        }
        {
            int kg = c * 64;
            const __nv_bfloat16* bh = WtHi + (size_t)(n0 + row) * K_TOT + kg;
            const __nv_bfloat16* bl = WtLo + (size_t)(n0 + row) * K_TOT + kg;
            #pragma unroll
            for (int j = j0; j < j0 + 4; j++) {
                uint32_t off = SMEM_SWIZZLE_128B((uint32_t)(row * 128 + j * 16));
                cp_async16(sb_hi + off, bh + j * 8, true);
                cp_async16(sb_lo + off, bl + j * 8, true);
            }
        }
        CP_COMMIT();
    };

    float acc[16][4];
    #pragma unroll
    for (int nt = 0; nt < 16; nt++)
        #pragma unroll
        for (int q = 0; q < 4; q++) acc[nt][q] = 0.f;

    load_chunk(0, 0);

    for (int c = 0; c < CHUNKS; c++) {
        int s = c & 1;
        if (c + 1 < CHUNKS) {
            load_chunk(c + 1, (c + 1) & 1);
            CP_WAIT(1);
        } else {
            CP_WAIT(0);
        }
        __syncthreads();

        uint32_t sa_hi = smem_to_u32(ST_A_HI(s));
        uint32_t sa_lo = smem_to_u32(ST_A_LO(s));
        uint32_t sb_hi = smem_to_u32(ST_B_HI(s));
        uint32_t sb_lo = smem_to_u32(ST_B_LO(s));

        #pragma unroll
        for (int ks = 0; ks < 4; ks++) {
            uint32_t ah[4], al[4];
            {
                int r  = wid * 16 + (lane & 7) + ((lane >> 3) & 1) * 8;
                int cb = ks * 32 + ((lane >> 4) & 1) * 16;
                uint32_t off = SMEM_SWIZZLE_128B((uint32_t)(r * 128 + cb));
                ldsm_x4(ah, sa_hi + off);
                ldsm_x4(al, sa_lo + off);
            }
            #pragma unroll
            for (int half = 0; half < 4; half++) {
                uint32_t bh[2][4], bl[2][4];
                #pragma unroll
                for (int q = 0; q < 2; q++) {
                    int nt0 = half * 4 + q * 2;
                    int r  = nt0 * 8 + (lane & 7) + ((lane >> 4) & 1) * 8;
                    int cb = ks * 32 + ((lane >> 3) & 1) * 16;
                    uint32_t off = SMEM_SWIZZLE_128B((uint32_t)(r * 128 + cb));
                    ldsm_x4(bh[q], sb_hi + off);
                    ldsm_x4(bl[q], sb_lo + off);
                }
                #pragma unroll
                for (int q = 0; q < 2; q++)
                    #pragma unroll
                    for (int sub = 0; sub < 2; sub++) {
                        int nt = half * 4 + q * 2 + sub;
                        mma_bf16(acc[nt], ah, &bh[q][sub * 2]);
                        mma_bf16(acc[nt], al, &bh[q][sub * 2]);
                        mma_bf16(acc[nt], ah, &bl[q][sub * 2]);
                    }
            }
        }
        __syncthreads();
    }

    // ---- epilogue ----
    int g = lane >> 2;
    int t = lane & 3;
    int r0 = m0 + wid * 16 + g;
    int r1 = r0 + 8;
    #pragma unroll
    for (int nt = 0; nt < 16; nt++) {
        int n = n0 + nt * 8 + 2 * t;          // global col in [0, N_TOT)
        if (MODE == 0) {
            float2 bb = *(const float2*)(bias + n);
            float c0 = fmaxf(acc[nt][0] + bb.x, 0.f);
            float c1 = fmaxf(acc[nt][1] + bb.y, 0.f);
            float c2 = fmaxf(acc[nt][2] + bb.x, 0.f);
            float c3 = fmaxf(acc[nt][3] + bb.y, 0.f);
            if (r0 < M) {
                __nv_bfloat16 h0, h1, l0, l1;
                split_f32(c0, h0, l0); split_f32(c1, h1, l1);
                *(__nv_bfloat162*)(CoutHi + (size_t)r0 * N_TOT + n) = __nv_bfloat162(h0, h1);
                *(__nv_bfloat162*)(CoutLo + (size_t)r0 * N_TOT + n) = __nv_bfloat162(l0, l1);
            }
            if (r1 < M) {
                __nv_bfloat16 h2, h3, l2, l3;
                split_f32(c2, h2, l2); split_f32(c3, h3, l3);
                *(__nv_bfloat162*)(CoutHi + (size_t)r1 * N_TOT + n) = __nv_bfloat162(h2, h3);
                *(__nv_bfloat162*)(CoutLo + (size_t)r1 * N_TOT + n) = __nv_bfloat162(l2, l3);
            }
        } else {
            // MODE 1: by=0 -> y2l (no bias), by=1 -> out (+bias)
            if (n < 128) {
                if (r0 < M) *(float2*)(OutF + (size_t)r0 * 128 + n) =
                    make_float2(acc[nt][0], acc[nt][1]);
                if (r1 < M) *(float2*)(OutF + (size_t)r1 * 128 + n) =
                    make_float2(acc[nt][2], acc[nt][3]);
            } else {
                int nn = n - 128;
                float2 bb = *(const float2*)(bias + nn);
                if (r0 < M) *(float2*)(OutF2 + (size_t)r0 * 128 + nn) =
                    make_float2(acc[nt][0] + bb.x, acc[nt][1] + bb.y);
                if (r1 < M) *(float2*)(OutF2 + (size_t)r1 * 128 + nn) =
                    make_float2(acc[nt][2] + bb.x, acc[nt][3] + bb.y);
            }
        }
    }
}

// ---------------------------------------------------------------------------
// Launch
// ---------------------------------------------------------------------------
extern "C" void kernel_launch(void* const* d_in, const int* in_sizes, int n_in,
                              void* d_out, int out_size)
{
    const float* x   = (const float*)d_in[0];
    const int*   ei  = (const int*)d_in[1];     // int32 (JAX x64 disabled)
    const float* W1l = (const float*)d_in[2];
    const float* b1  = (const float*)d_in[3];
    const float* W1r = (const float*)d_in[4];
    const float* W2l = (const float*)d_in[5];
    const float* b2  = (const float*)d_in[6];
    const float* W2r = (const float*)d_in[7];
    float*       out = (float*)d_out;

    const int* src = ei;
    const int* dst = ei + N_EDGES;

    int* cnt_int;
    float* y2l;
    __nv_bfloat16 *xhi, *xlo, *a1hi, *a1lo, *hhi, *hlo;
    __nv_bfloat16 *wt1h, *wt1l, *wt2h, *wt2l;
    cudaGetSymbolAddress((void**)&cnt_int, g_cnt_int);
    cudaGetSymbolAddress((void**)&y2l,  g_y2l);
    cudaGetSymbolAddress((void**)&xhi,  g_x_hi);
    cudaGetSymbolAddress((void**)&xlo,  g_x_lo);
    cudaGetSymbolAddress((void**)&a1hi, g_a1_hi);
    cudaGetSymbolAddress((void**)&a1lo, g_a1_lo);
    cudaGetSymbolAddress((void**)&hhi,  g_h_hi);
    cudaGetSymbolAddress((void**)&hlo,  g_h_lo);
    cudaGetSymbolAddress((void**)&wt1h, g_wt1_hi);
    cudaGetSymbolAddress((void**)&wt1l, g_wt1_lo);
    cudaGetSymbolAddress((void**)&wt2h, g_wt2_hi);
    cudaGetSymbolAddress((void**)&wt2l, g_wt2_lo);

    auto gemm1 = sage_mma_warp<256, 2, 256, 0>;
    auto gemm2 = sage_mma_warp<256, 1, 256, 1>;
    cudaFuncSetAttribute(gemm1, cudaFuncAttributeMaxDynamicSharedMemorySize, MMA_SMEM_TOTAL);
    cudaFuncSetAttribute(gemm2, cudaFuncAttributeMaxDynamicSharedMemorySize, MMA_SMEM_TOTAL);

    const int NB = (N_NODES + 255) / 256;
    int mgrid = (N_NODES + 127) / 128;

    // ---- CSR build ----
    zero_int_kernel<<<NB, 256>>>(cnt_int, N_NODES);
    hist_kernel<<<(N_EDGES + 255) / 256, 256>>>(dst);
    scan_stage1_kernel<<<NB, 256>>>();
    scan_stage2_kernel<<<1, 256>>>(NB);
    scan_stage3_kernel<<<NB, 256>>>();
    fill_kernel<<<(N_EDGES + 255) / 256, 256>>>(src, dst);

    // ---- feature + weight splits ----
    {
        int n4 = N_NODES * IN_C / 4;
        split_feat_kernel<<<(n4 + 255) / 256, 256>>>(x, xhi, xlo, n4);
    }
    prep_w1_kernel<<<(HID_C * 256 + 255) / 256, 256>>>(W1l, W1r, wt1h, wt1l);
    prep_w2_kernel<<<(256 * HID_C + 255) / 256, 256>>>(W2l, W2r, wt2h, wt2l);

    // ---- layer 1: gather x -> a1, then [a1|x] @ wt1 -> h (split bf16) ----
    {
        int warps_per_block = 8;
        int grid = (N_NODES + warps_per_block - 1) / warps_per_block;
        gather_bf16_kernel<IN_C><<<grid, warps_per_block * 32>>>(xhi, xlo, a1hi, a1lo);
    }
    {
        dim3 grid(mgrid, 2);
        gemm1<<<grid, 256, MMA_SMEM_TOTAL>>>(
            a1hi, a1lo, xhi, xlo, wt1h, wt1l, b1,
            nullptr, nullptr, hhi, hlo, N_NODES);
    }

    // ---- layer 2 (gather commuted): h @ [W2l|W2r] -> y2l, out(+b2) ----
    {
        dim3 grid(mgrid, 2);
        gemm2<<<grid, 256, MMA_SMEM_TOTAL>>>(
            hhi, hlo, nullptr, nullptr, wt2h, wt2l, b2,
            y2l, out, nullptr, nullptr, N_NODES);
    }
    // out += mean-gather(y2l)
    {
        int warps_per_block = 8;
        int grid = (N_NODES + warps_per_block - 1) / warps_per_block;
        gather_acc_kernel<<<grid, warps_per_block * 32>>>(y2l, out);
    }
}

// round 13
// speedup vs baseline: 3.1226x; 1.1794x over previous
#include <cuda_runtime.h>
#include <cuda_fp16.h>
#include <cstdint>

// Problem constants (match reference_code)
#define IN_C    128
#define HID_C   256
#define OUT_C   128
#define N_NODES 50000
#define N_EDGES 600000

// ---------------------------------------------------------------------------
// Scratch (no cudaMalloc allowed): device globals
// ---------------------------------------------------------------------------
__device__ int g_cnt_int  [N_NODES];
__device__ int g_row_start[N_NODES + 1];
__device__ int g_cursor   [N_NODES];
__device__ int g_csr_src  [N_EDGES];
__device__ int g_bsum     [256];

// Split fp16 feature pipeline (hi+lo = 22-bit effective precision)
__device__ __half g_x_hi [(size_t)N_NODES * IN_C];
__device__ __half g_x_lo [(size_t)N_NODES * IN_C];
__device__ __half g_a1_hi[(size_t)N_NODES * IN_C];
__device__ __half g_a1_lo[(size_t)N_NODES * IN_C];
__device__ __half g_h_hi [(size_t)N_NODES * HID_C];
__device__ __half g_h_lo [(size_t)N_NODES * HID_C];
__device__ float  g_y2l  [(size_t)N_NODES * OUT_C];   // h @ W2l (fp32)

// Pre-truncated transposed weights (fp16, single precision piece):
//  wt1[n][k], n in [0,256), k in [0,256): k<128 -> W1l[k][n], else W1r[k-128][n]
//  wt2[n][k], n in [0,256), k in [0,256): n<128 -> W2l[k][n], else W2r[k][n-128]
__device__ __half g_wt1[HID_C * (2 * IN_C)];
__device__ __half g_wt2[(2 * OUT_C) * HID_C];

// ---------------------------------------------------------------------------
// Helpers
// ---------------------------------------------------------------------------
__device__ __forceinline__ uint32_t smem_to_u32(const void* p) {
    uint32_t a;
    asm("{ .reg .u64 t; cvta.to.shared.u64 t, %1; cvt.u32.u64 %0, t; }" : "=r"(a) : "l"(p));
    return a;
}

#define SMEM_SWIZZLE_128B(off) ((off) ^ (((off) >> 3) & 0x70))

__device__ __forceinline__ void ldsm_x4(uint32_t* r, uint32_t addr) {
    asm volatile("ldmatrix.sync.aligned.m8n8.x4.shared.b16 {%0,%1,%2,%3}, [%4];"
        : "=r"(r[0]), "=r"(r[1]), "=r"(r[2]), "=r"(r[3]) : "r"(addr));
}

__device__ __forceinline__ void mma_f16(float* c, const uint32_t* a, const uint32_t* b) {
    asm volatile("mma.sync.aligned.m16n8k16.row.col.f32.f16.f16.f32 "
        "{%0,%1,%2,%3}, {%4,%5,%6,%7}, {%8,%9}, {%0,%1,%2,%3};"
        : "+f"(c[0]), "+f"(c[1]), "+f"(c[2]), "+f"(c[3])
        : "r"(a[0]), "r"(a[1]), "r"(a[2]), "r"(a[3]), "r"(b[0]), "r"(b[1]));
}

__device__ __forceinline__ void cp_async16(uint32_t smem, const void* g, bool valid) {
    int sz = valid ? 16 : 0;
    asm volatile("cp.async.cg.shared.global [%0], [%1], 16, %2;"
        :: "r"(smem), "l"(g), "r"(sz) : "memory");
}
#define CP_COMMIT() asm volatile("cp.async.commit_group;" ::: "memory")
#define CP_WAIT(n)  asm volatile("cp.async.wait_group %0;" :: "n"(n) : "memory")

// split one fp32 into hi/lo fp16 (22-bit total)
__device__ __forceinline__ void split_f32(float v, __half& h, __half& l) {
    h = __float2half_rn(v);
    l = __float2half_rn(v - __half2float(h));
}

// ---------------------------------------------------------------------------
// CSR build
// ---------------------------------------------------------------------------
__global__ void zero_int_kernel(int* __restrict__ p, int n)
{
    int i = blockIdx.x * blockDim.x + threadIdx.x;
    if (i < n) p[i] = 0;
}

__global__ void hist_kernel(const int* __restrict__ dst)
{
    int e = blockIdx.x * blockDim.x + threadIdx.x;
    if (e < N_EDGES) atomicAdd(&g_cnt_int[dst[e]], 1);
}

__global__ void scan_stage1_kernel()
{
    __shared__ int sdata[256];
    int tid = threadIdx.x;
    int i = blockIdx.x * 256 + tid;
    int v = (i < N_NODES) ? g_cnt_int[i] : 0;
    sdata[tid] = v;
    __syncthreads();
    #pragma unroll
    for (int s = 1; s < 256; s <<= 1) {
        int t = (tid >= s) ? sdata[tid - s] : 0;
        __syncthreads();
        sdata[tid] += t;
        __syncthreads();
    }
    if (i < N_NODES) g_row_start[i] = sdata[tid] - v;
    if (tid == 255) g_bsum[blockIdx.x] = sdata[255];
}

__global__ void scan_stage2_kernel(int nblocks)
{
    __shared__ int sdata[256];
    int tid = threadIdx.x;
    int v = (tid < nblocks) ? g_bsum[tid] : 0;
    sdata[tid] = v;
    __syncthreads();
    #pragma unroll
    for (int s = 1; s < 256; s <<= 1) {
        int t = (tid >= s) ? sdata[tid - s] : 0;
        __syncthreads();
        sdata[tid] += t;
        __syncthreads();
    }
    if (tid < nblocks) g_bsum[tid] = sdata[tid] - v;
    if (tid == 255) g_row_start[N_NODES] = sdata[255];
}

__global__ void scan_stage3_kernel()
{
    int i = blockIdx.x * blockDim.x + threadIdx.x;
    if (i < N_NODES) {
        int rs = g_row_start[i] + g_bsum[blockIdx.x];
        g_row_start[i] = rs;
        g_cursor[i]    = rs;
    }
}

__global__ void fill_kernel(const int* __restrict__ src, const int* __restrict__ dst)
{
    int e = blockIdx.x * blockDim.x + threadIdx.x;
    if (e < N_EDGES) {
        int pos = atomicAdd(&g_cursor[dst[e]], 1);
        g_csr_src[pos] = src[e];
    }
}

// ---------------------------------------------------------------------------
// Split fp32 features -> hi/lo fp16
// ---------------------------------------------------------------------------
__global__ void split_feat_kernel(const float* __restrict__ in,
                                  __half* __restrict__ hi,
                                  __half* __restrict__ lo,
                                  int n4)
{
    int i = blockIdx.x * blockDim.x + threadIdx.x;
    if (i >= n4) return;
    float4 v = *(const float4*)(in + i * 4);
    __half h0, h1, h2, h3, l0, l1, l2, l3;
    split_f32(v.x, h0, l0); split_f32(v.y, h1, l1);
    split_f32(v.z, h2, l2); split_f32(v.w, h3, l3);
    __half2* ph = (__half2*)(hi + i * 4);
    __half2* pl = (__half2*)(lo + i * 4);
    ph[0] = __halves2half2(h0, h1); ph[1] = __halves2half2(h2, h3);
    pl[0] = __halves2half2(l0, l1); pl[1] = __halves2half2(l2, l3);
}

// ---------------------------------------------------------------------------
// Gather-aggregate (layer 1): split fp16 in -> split fp16 mean out
// ---------------------------------------------------------------------------
template<int C>
__global__ void gather_f16_kernel(const __half* __restrict__ fhi,
                                  const __half* __restrict__ flo,
                                  __half* __restrict__ ahi,
                                  __half* __restrict__ alo)
{
    int node = blockIdx.x * (blockDim.x >> 5) + (threadIdx.x >> 5);
    if (node >= N_NODES) return;
    int lane = threadIdx.x & 31;
    int beg = g_row_start[node];
    int end = g_row_start[node + 1];

    constexpr int V = C / 128;
    float4 acc[V];
    #pragma unroll
    for (int v = 0; v < V; v++) acc[v] = make_float4(0.f, 0.f, 0.f, 0.f);

    for (int k = beg; k < end; k++) {
        int s = g_csr_src[k];
        const uint2* ph = (const uint2*)(fhi + (size_t)s * C);
        const uint2* pl = (const uint2*)(flo + (size_t)s * C);
        #pragma unroll
        for (int v = 0; v < V; v++) {
            uint2 hw = ph[lane + 32 * v];
            uint2 lw = pl[lane + 32 * v];
            float2 h0 = __half22float2(*(__half2*)&hw.x);
            float2 h1 = __half22float2(*(__half2*)&hw.y);
            float2 l0 = __half22float2(*(__half2*)&lw.x);
            float2 l1 = __half22float2(*(__half2*)&lw.y);
            acc[v].x += h0.x + l0.x;
            acc[v].y += h0.y + l0.y;
            acc[v].z += h1.x + l1.x;
            acc[v].w += h1.y + l1.y;
        }
    }
    float inv = 1.0f / (float)max(end - beg, 1);
    #pragma unroll
    for (int v = 0; v < V; v++) {
        float4 a = acc[v];
        a.x *= inv; a.y *= inv; a.z *= inv; a.w *= inv;
        __half h0, h1, h2, h3, l0, l1, l2, l3;
        split_f32(a.x, h0, l0); split_f32(a.y, h1, l1);
        split_f32(a.z, h2, l2); split_f32(a.w, h3, l3);
        uint2 hw, lw;
        *(__half2*)&hw.x = __halves2half2(h0, h1);
        *(__half2*)&hw.y = __halves2half2(h2, h3);
        *(__half2*)&lw.x = __halves2half2(l0, l1);
        *(__half2*)&lw.y = __halves2half2(l2, l3);
        ((uint2*)(ahi + (size_t)node * C))[lane + 32 * v] = hw;
        ((uint2*)(alo + (size_t)node * C))[lane + 32 * v] = lw;
    }
}

// ---------------------------------------------------------------------------
// Layer-2 gather (commuted): out[node] += mean over in-edges of y2l[src]
// ---------------------------------------------------------------------------
__global__ void gather_acc_kernel(const float* __restrict__ y2l,
                                  float* __restrict__ out)
{
    int node = blockIdx.x * (blockDim.x >> 5) + (threadIdx.x >> 5);
    if (node >= N_NODES) return;
    int lane = threadIdx.x & 31;
    int beg = g_row_start[node];
    int end = g_row_start[node + 1];

    float4 acc = make_float4(0.f, 0.f, 0.f, 0.f);
    for (int k = beg; k < end; k++) {
        int s = g_csr_src[k];
        float4 v = ((const float4*)(y2l + (size_t)s * OUT_C))[lane];
        acc.x += v.x; acc.y += v.y; acc.z += v.z; acc.w += v.w;
    }
    float inv = 1.0f / (float)max(end - beg, 1);
    float4* o = (float4*)(out + (size_t)node * OUT_C) + lane;
    float4 p = *o;
    p.x += acc.x * inv; p.y += acc.y * inv;
    p.z += acc.z * inv; p.w += acc.w * inv;
    *o = p;
}

// ---------------------------------------------------------------------------
// Weight prep (fp16 truncation only — no lo piece needed)
// ---------------------------------------------------------------------------
__global__ void prep_w1_kernel(const float* __restrict__ W1l,
                               const float* __restrict__ W1r,
                               __half* __restrict__ w)
{
    int idx = blockIdx.x * blockDim.x + threadIdx.x;
    if (idx >= HID_C * 256) return;
    int n = idx / 256;
    int k = idx % 256;
    float v = (k < 128) ? W1l[(size_t)k * HID_C + n] : W1r[(size_t)(k - 128) * HID_C + n];
    w[idx] = __float2half_rn(v);
}

__global__ void prep_w2_kernel(const float* __restrict__ W2l,
                               const float* __restrict__ W2r,
                               __half* __restrict__ w)
{
    int idx = blockIdx.x * blockDim.x + threadIdx.x;
    if (idx >= 256 * HID_C) return;
    int n = idx / HID_C;          // 0..255 output col (0-127 y2l, 128-255 y2r)
    int k = idx % HID_C;
    float v = (n < 128) ? W2l[(size_t)k * OUT_C + n] : W2r[(size_t)k * OUT_C + (n - 128)];
    w[idx] = __float2half_rn(v);
}

// ---------------------------------------------------------------------------
// Pipelined warp-MMA GEMM, CTA tile 128(M) x 128(N), 8 warps, 2 stages.
// fp16 2-term split: acc = Ah*Bh + Al*Bh  (= A(22-bit) * B(fp16)).
// K_TOT in chunks of 64. HALVES=2: A=[A0|A1]; HALVES=1: A=A0.
// MODE 0 (layer1): h-out = relu(acc + bias) -> split fp16.
// MODE 1 (layer2): cols<128 -> y2l fp32 (no bias); cols>=128 -> out fp32 +bias.
// SMEM per stage: Ahi 16K | Alo 16K | Bh 16K = 48KB; 2 stages = 96KB.
// ---------------------------------------------------------------------------
#define ST_A_HI(s) (smem_raw + (s) * 49152)
#define ST_A_LO(s) (smem_raw + (s) * 49152 + 16384)
#define ST_B_HI(s) (smem_raw + (s) * 49152 + 32768)
#define MMA_SMEM_TOTAL 98304

template<int K_TOT, int HALVES, int N_TOT, int MODE>
__global__ __launch_bounds__(256)
void sage_mma_warp(const __half* __restrict__ A0Hi,
                   const __half* __restrict__ A0Lo,
                   const __half* __restrict__ A1Hi,
                   const __half* __restrict__ A1Lo,
                   const __half* __restrict__ Wt,
                   const float* __restrict__ bias,
                   float* __restrict__ OutF,      // MODE1: y2l
                   float* __restrict__ OutF2,     // MODE1: out
                   __half* __restrict__ CoutHi,
                   __half* __restrict__ CoutLo,
                   int M)
{
    extern __shared__ char smem_raw[];
    constexpr int CHUNKS = K_TOT / 64;
    constexpr int K_SRC  = K_TOT / HALVES;

    int tid  = threadIdx.x;
    int wid  = tid >> 5;
    int lane = tid & 31;
    int m0 = blockIdx.x * 128;
    int n0 = blockIdx.y * 128;

    auto load_chunk = [&](int c, int s) {
        uint32_t sa_hi = smem_to_u32(ST_A_HI(s));
        uint32_t sa_lo = smem_to_u32(ST_A_LO(s));
        uint32_t sb_hi = smem_to_u32(ST_B_HI(s));
        int row = tid >> 1;
        int j0  = (tid & 1) * 4;
        {
            bool first_src = (HALVES == 1) || (c < CHUNKS / 2);
            const __half* Ah = first_src ? A0Hi : A1Hi;
            const __half* Al = first_src ? A0Lo : A1Lo;
            int k0 = (first_src ? c : c - CHUNKS / 2) * 64;
            int gm = m0 + row;
            bool valid = gm < M;
            const __half* ph = Ah + (size_t)gm * K_SRC + k0;
            const __half* pl = Al + (size_t)gm * K_SRC + k0;
            #pragma unroll
            for (int j = j0; j < j0 + 4; j++) {
                uint32_t off = SMEM_SWIZZLE_128B((uint32_t)(row * 128 + j * 16));
                cp_async16(sa_hi + off, ph + j * 8, valid);
                cp_async16(sa_lo + off, pl + j * 8, valid);
            }
        }
        {
            int kg = c * 64;
            const __half* bh = Wt + (size_t)(n0 + row) * K_TOT + kg;
            #pragma unroll
            for (int j = j0; j < j0 + 4; j++) {
                uint32_t off = SMEM_SWIZZLE_128B((uint32_t)(row * 128 + j * 16));
                cp_async16(sb_hi + off, bh + j * 8, true);
            }
        }
        CP_COMMIT();
    };

    float acc[16][4];
    #pragma unroll
    for (int nt = 0; nt < 16; nt++)
        #pragma unroll
        for (int q = 0; q < 4; q++) acc[nt][q] = 0.f;

    load_chunk(0, 0);

    for (int c = 0; c < CHUNKS; c++) {
        int s = c & 1;
        if (c + 1 < CHUNKS) {
            load_chunk(c + 1, (c + 1) & 1);
            CP_WAIT(1);
        } else {
            CP_WAIT(0);
        }
        __syncthreads();

        uint32_t sa_hi = smem_to_u32(ST_A_HI(s));
        uint32_t sa_lo = smem_to_u32(ST_A_LO(s));
        uint32_t sb_hi = smem_to_u32(ST_B_HI(s));

        #pragma unroll
        for (int ks = 0; ks < 4; ks++) {
            uint32_t ah[4], al[4];
            {
                int r  = wid * 16 + (lane & 7) + ((lane >> 3) & 1) * 8;
                int cb = ks * 32 + ((lane >> 4) & 1) * 16;
                uint32_t off = SMEM_SWIZZLE_128B((uint32_t)(r * 128 + cb));
                ldsm_x4(ah, sa_hi + off);
                ldsm_x4(al, sa_lo + off);
            }
            #pragma unroll
            for (int half = 0; half < 4; half++) {
                uint32_t bh[2][4];
                #pragma unroll
                for (int q = 0; q < 2; q++) {
                    int nt0 = half * 4 + q * 2;
                    int r  = nt0 * 8 + (lane & 7) + ((lane >> 4) & 1) * 8;
                    int cb = ks * 32 + ((lane >> 3) & 1) * 16;
                    uint32_t off = SMEM_SWIZZLE_128B((uint32_t)(r * 128 + cb));
                    ldsm_x4(bh[q], sb_hi + off);
                }
                #pragma unroll
                for (int q = 0; q < 2; q++)
                    #pragma unroll
                    for (int sub = 0; sub < 2; sub++) {
                        int nt = half * 4 + q * 2 + sub;
                        mma_f16(acc[nt], ah, &bh[q][sub * 2]);
                        mma_f16(acc[nt], al, &bh[q][sub * 2]);
                    }
            }
        }
        __syncthreads();
    }

    // ---- epilogue ----
    int g = lane >> 2;
    int t = lane & 3;
    int r0 = m0 + wid * 16 + g;
    int r1 = r0 + 8;
    #pragma unroll
    for (int nt = 0; nt < 16; nt++) {
        int n = n0 + nt * 8 + 2 * t;
        if (MODE == 0) {
            float2 bb = *(const float2*)(bias + n);
            float c0 = fmaxf(acc[nt][0] + bb.x, 0.f);
            float c1 = fmaxf(acc[nt][1] + bb.y, 0.f);
            float c2 = fmaxf(acc[nt][2] + bb.x, 0.f);
            float c3 = fmaxf(acc[nt][3] + bb.y, 0.f);
            if (r0 < M) {
                __half h0, h1, l0, l1;
                split_f32(c0, h0, l0); split_f32(c1, h1, l1);
                *(__half2*)(CoutHi + (size_t)r0 * N_TOT + n) = __halves2half2(h0, h1);
                *(__half2*)(CoutLo + (size_t)r0 * N_TOT + n) = __halves2half2(l0, l1);
            }
            if (r1 < M) {
                __half h2, h3, l2, l3;
                split_f32(c2, h2, l2); split_f32(c3, h3, l3);
                *(__half2*)(CoutHi + (size_t)r1 * N_TOT + n) = __halves2half2(h2, h3);
                *(__half2*)(CoutLo + (size_t)r1 * N_TOT + n) = __halves2half2(l2, l3);
            }
        } else {
            if (n < 128) {
                if (r0 < M) *(float2*)(OutF + (size_t)r0 * 128 + n) =
                    make_float2(acc[nt][0], acc[nt][1]);
                if (r1 < M) *(float2*)(OutF + (size_t)r1 * 128 + n) =
                    make_float2(acc[nt][2], acc[nt][3]);
            } else {
                int nn = n - 128;
                float2 bb = *(const float2*)(bias + nn);
                if (r0 < M) *(float2*)(OutF2 + (size_t)r0 * 128 + nn) =
                    make_float2(acc[nt][0] + bb.x, acc[nt][1] + bb.y);
                if (r1 < M) *(float2*)(OutF2 + (size_t)r1 * 128 + nn) =
                    make_float2(acc[nt][2] + bb.x, acc[nt][3] + bb.y);
            }
        }
    }
}

// ---------------------------------------------------------------------------
// Launch
// ---------------------------------------------------------------------------
extern "C" void kernel_launch(void* const* d_in, const int* in_sizes, int n_in,
                              void* d_out, int out_size)
{
    const float* x   = (const float*)d_in[0];
    const int*   ei  = (const int*)d_in[1];     // int32 (JAX x64 disabled)
    const float* W1l = (const float*)d_in[2];
    const float* b1  = (const float*)d_in[3];
    const float* W1r = (const float*)d_in[4];
    const float* W2l = (const float*)d_in[5];
    const float* b2  = (const float*)d_in[6];
    const float* W2r = (const float*)d_in[7];
    float*       out = (float*)d_out;

    const int* src = ei;
    const int* dst = ei + N_EDGES;

    int* cnt_int;
    float* y2l;
    __half *xhi, *xlo, *a1hi, *a1lo, *hhi, *hlo, *wt1, *wt2;
    cudaGetSymbolAddress((void**)&cnt_int, g_cnt_int);
    cudaGetSymbolAddress((void**)&y2l,  g_y2l);
    cudaGetSymbolAddress((void**)&xhi,  g_x_hi);
    cudaGetSymbolAddress((void**)&xlo,  g_x_lo);
    cudaGetSymbolAddress((void**)&a1hi, g_a1_hi);
    cudaGetSymbolAddress((void**)&a1lo, g_a1_lo);
    cudaGetSymbolAddress((void**)&hhi,  g_h_hi);
    cudaGetSymbolAddress((void**)&hlo,  g_h_lo);
    cudaGetSymbolAddress((void**)&wt1,  g_wt1);
    cudaGetSymbolAddress((void**)&wt2,  g_wt2);

    auto gemm1 = sage_mma_warp<256, 2, 256, 0>;
    auto gemm2 = sage_mma_warp<256, 1, 256, 1>;
    cudaFuncSetAttribute(gemm1, cudaFuncAttributeMaxDynamicSharedMemorySize, MMA_SMEM_TOTAL);
    cudaFuncSetAttribute(gemm2, cudaFuncAttributeMaxDynamicSharedMemorySize, MMA_SMEM_TOTAL);

    const int NB = (N_NODES + 255) / 256;
    int mgrid = (N_NODES + 127) / 128;

    // ---- CSR build ----
    zero_int_kernel<<<NB, 256>>>(cnt_int, N_NODES);
    hist_kernel<<<(N_EDGES + 255) / 256, 256>>>(dst);
    scan_stage1_kernel<<<NB, 256>>>();
    scan_stage2_kernel<<<1, 256>>>(NB);
    scan_stage3_kernel<<<NB, 256>>>();
    fill_kernel<<<(N_EDGES + 255) / 256, 256>>>(src, dst);

    // ---- feature + weight prep ----
    {
        int n4 = N_NODES * IN_C / 4;
        split_feat_kernel<<<(n4 + 255) / 256, 256>>>(x, xhi, xlo, n4);
    }
    prep_w1_kernel<<<(HID_C * 256 + 255) / 256, 256>>>(W1l, W1r, wt1);
    prep_w2_kernel<<<(256 * HID_C + 255) / 256, 256>>>(W2l, W2r, wt2);

    // ---- layer 1: gather x -> a1, then [a1|x] @ wt1 -> h (split fp16) ----
    {
        int warps_per_block = 8;
        int grid = (N_NODES + warps_per_block - 1) / warps_per_block;
        gather_f16_kernel<IN_C><<<grid, warps_per_block * 32>>>(xhi, xlo, a1hi, a1lo);
    }
    {
        dim3 grid(mgrid, 2);
        gemm1<<<grid, 256, MMA_SMEM_TOTAL>>>(
            a1hi, a1lo, xhi, xlo, wt1, b1,
            nullptr, nullptr, hhi, hlo, N_NODES);
    }

    // ---- layer 2 (gather commuted): h @ [W2l|W2r] -> y2l, out(+b2) ----
    {
        dim3 grid(mgrid, 2);
        gemm2<<<grid, 256, MMA_SMEM_TOTAL>>>(
            hhi, hlo, nullptr, nullptr, wt2, b2,
            y2l, out, nullptr, nullptr, N_NODES);
    }
    // out += mean-gather(y2l)
    {
        int warps_per_block = 8;
        int grid = (N_NODES + warps_per_block - 1) / warps_per_block;
        gather_acc_kernel<<<grid, warps_per_block * 32>>>(y2l, out);
    }
}

// round 14
// speedup vs baseline: 3.2355x; 1.0362x over previous
#include <cuda_runtime.h>
#include <cuda_fp16.h>
#include <cstdint>

// Problem constants (match reference_code)
#define IN_C    128
#define HID_C   256
#define OUT_C   128
#define N_NODES 50000
#define N_EDGES 600000

// ---------------------------------------------------------------------------
// Scratch (no cudaMalloc allowed): device globals
// ---------------------------------------------------------------------------
__device__ int g_cnt_int  [N_NODES];     // zero at entry (restored by scan_stage1)
__device__ int g_row_start[N_NODES + 1];
__device__ int g_cursor   [N_NODES];
__device__ int g_csr_src  [N_EDGES];
__device__ int g_bsum     [256];

// Split fp16 feature pipeline (hi+lo = 22-bit effective precision)
__device__ __half g_x_hi [(size_t)N_NODES * IN_C];
__device__ __half g_x_lo [(size_t)N_NODES * IN_C];
__device__ __half g_a1_hi[(size_t)N_NODES * IN_C];
__device__ __half g_a1_lo[(size_t)N_NODES * IN_C];
__device__ __half g_h_hi [(size_t)N_NODES * HID_C];
__device__ __half g_h_lo [(size_t)N_NODES * HID_C];
__device__ __half g_y2l  [(size_t)N_NODES * OUT_C];   // h @ W2l (fp16)

// Pre-truncated transposed weights (fp16):
//  wt1[n][k], n in [0,256), k in [0,256): k<128 -> W1l[k][n], else W1r[k-128][n]
//  wt2[n][k], n in [0,256), k in [0,256): n<128 -> W2l[k][n], else W2r[k][n-128]
__device__ __half g_wt1[HID_C * (2 * IN_C)];
__device__ __half g_wt2[(2 * OUT_C) * HID_C];

// ---------------------------------------------------------------------------
// Helpers
// ---------------------------------------------------------------------------
__device__ __forceinline__ uint32_t smem_to_u32(const void* p) {
    uint32_t a;
    asm("{ .reg .u64 t; cvta.to.shared.u64 t, %1; cvt.u32.u64 %0, t; }" : "=r"(a) : "l"(p));
    return a;
}

#define SMEM_SWIZZLE_128B(off) ((off) ^ (((off) >> 3) & 0x70))

__device__ __forceinline__ void ldsm_x4(uint32_t* r, uint32_t addr) {
    asm volatile("ldmatrix.sync.aligned.m8n8.x4.shared.b16 {%0,%1,%2,%3}, [%4];"
        : "=r"(r[0]), "=r"(r[1]), "=r"(r[2]), "=r"(r[3]) : "r"(addr));
}

__device__ __forceinline__ void mma_f16(float* c, const uint32_t* a, const uint32_t* b) {
    asm volatile("mma.sync.aligned.m16n8k16.row.col.f32.f16.f16.f32 "
        "{%0,%1,%2,%3}, {%4,%5,%6,%7}, {%8,%9}, {%0,%1,%2,%3};"
        : "+f"(c[0]), "+f"(c[1]), "+f"(c[2]), "+f"(c[3])
        : "r"(a[0]), "r"(a[1]), "r"(a[2]), "r"(a[3]), "r"(b[0]), "r"(b[1]));
}

__device__ __forceinline__ void cp_async16(uint32_t smem, const void* g, bool valid) {
    int sz = valid ? 16 : 0;
    asm volatile("cp.async.cg.shared.global [%0], [%1], 16, %2;"
        :: "r"(smem), "l"(g), "r"(sz) : "memory");
}
#define CP_COMMIT() asm volatile("cp.async.commit_group;" ::: "memory")
#define CP_WAIT(n)  asm volatile("cp.async.wait_group %0;" :: "n"(n) : "memory")

// split one fp32 into hi/lo fp16 (22-bit total)
__device__ __forceinline__ void split_f32(float v, __half& h, __half& l) {
    h = __float2half_rn(v);
    l = __float2half_rn(v - __half2float(h));
}

// ---------------------------------------------------------------------------
// CSR build
// ---------------------------------------------------------------------------
__global__ void hist_kernel(const int* __restrict__ dst)
{
    int e = blockIdx.x * blockDim.x + threadIdx.x;
    if (e < N_EDGES) atomicAdd(&g_cnt_int[dst[e]], 1);
}

// Stage 1: per-block exclusive scan + block sum. Also zeroes cnt_int after
// reading, restoring the "zero at entry" invariant for the next replay.
__global__ void scan_stage1_kernel()
{
    __shared__ int sdata[256];
    int tid = threadIdx.x;
    int i = blockIdx.x * 256 + tid;
    int v = (i < N_NODES) ? g_cnt_int[i] : 0;
    if (i < N_NODES) g_cnt_int[i] = 0;
    sdata[tid] = v;
    __syncthreads();
    #pragma unroll
    for (int s = 1; s < 256; s <<= 1) {
        int t = (tid >= s) ? sdata[tid - s] : 0;
        __syncthreads();
        sdata[tid] += t;
        __syncthreads();
    }
    if (i < N_NODES) g_row_start[i] = sdata[tid] - v;
    if (tid == 255) g_bsum[blockIdx.x] = sdata[255];
}

__global__ void scan_stage2_kernel(int nblocks)
{
    __shared__ int sdata[256];
    int tid = threadIdx.x;
    int v = (tid < nblocks) ? g_bsum[tid] : 0;
    sdata[tid] = v;
    __syncthreads();
    #pragma unroll
    for (int s = 1; s < 256; s <<= 1) {
        int t = (tid >= s) ? sdata[tid - s] : 0;
        __syncthreads();
        sdata[tid] += t;
        __syncthreads();
    }
    if (tid < nblocks) g_bsum[tid] = sdata[tid] - v;
    if (tid == 255) g_row_start[N_NODES] = sdata[255];
}

__global__ void scan_stage3_kernel()
{
    int i = blockIdx.x * blockDim.x + threadIdx.x;
    if (i < N_NODES) {
        int rs = g_row_start[i] + g_bsum[blockIdx.x];
        g_row_start[i] = rs;
        g_cursor[i]    = rs;
    }
}

__global__ void fill_kernel(const int* __restrict__ src, const int* __restrict__ dst)
{
    int e = blockIdx.x * blockDim.x + threadIdx.x;
    if (e < N_EDGES) {
        int pos = atomicAdd(&g_cursor[dst[e]], 1);
        g_csr_src[pos] = src[e];
    }
}

// ---------------------------------------------------------------------------
// Split fp32 features -> hi/lo fp16
// ---------------------------------------------------------------------------
__global__ void split_feat_kernel(const float* __restrict__ in,
                                  __half* __restrict__ hi,
                                  __half* __restrict__ lo,
                                  int n4)
{
    int i = blockIdx.x * blockDim.x + threadIdx.x;
    if (i >= n4) return;
    float4 v = *(const float4*)(in + i * 4);
    __half h0, h1, h2, h3, l0, l1, l2, l3;
    split_f32(v.x, h0, l0); split_f32(v.y, h1, l1);
    split_f32(v.z, h2, l2); split_f32(v.w, h3, l3);
    __half2* ph = (__half2*)(hi + i * 4);
    __half2* pl = (__half2*)(lo + i * 4);
    ph[0] = __halves2half2(h0, h1); ph[1] = __halves2half2(h2, h3);
    pl[0] = __halves2half2(l0, l1); pl[1] = __halves2half2(l2, l3);
}

// ---------------------------------------------------------------------------
// Combined weight prep (both layers in one launch)
// ---------------------------------------------------------------------------
__global__ void prep_w_kernel(const float* __restrict__ W1l,
                              const float* __restrict__ W1r,
                              const float* __restrict__ W2l,
                              const float* __restrict__ W2r)
{
    int idx = blockIdx.x * blockDim.x + threadIdx.x;
    const int T1 = HID_C * 256;        // 65536
    if (idx < T1) {
        int n = idx / 256;
        int k = idx % 256;
        float v = (k < 128) ? W1l[(size_t)k * HID_C + n]
                            : W1r[(size_t)(k - 128) * HID_C + n];
        g_wt1[idx] = __float2half_rn(v);
    } else {
        idx -= T1;
        if (idx >= 256 * HID_C) return;
        int n = idx / HID_C;           // 0..255 output col (0-127 y2l, 128-255 y2r)
        int k = idx % HID_C;
        float v = (n < 128) ? W2l[(size_t)k * OUT_C + n]
                            : W2r[(size_t)k * OUT_C + (n - 128)];
        g_wt2[idx] = __float2half_rn(v);
    }
}

// ---------------------------------------------------------------------------
// Gather-aggregate (layer 1): split fp16 in -> split fp16 mean out
// ---------------------------------------------------------------------------
template<int C>
__global__ void gather_f16_kernel(const __half* __restrict__ fhi,
                                  const __half* __restrict__ flo,
                                  __half* __restrict__ ahi,
                                  __half* __restrict__ alo)
{
    int node = blockIdx.x * (blockDim.x >> 5) + (threadIdx.x >> 5);
    if (node >= N_NODES) return;
    int lane = threadIdx.x & 31;
    int beg = g_row_start[node];
    int end = g_row_start[node + 1];

    constexpr int V = C / 128;
    float4 acc[V];
    #pragma unroll
    for (int v = 0; v < V; v++) acc[v] = make_float4(0.f, 0.f, 0.f, 0.f);

    for (int k = beg; k < end; k++) {
        int s = g_csr_src[k];
        const uint2* ph = (const uint2*)(fhi + (size_t)s * C);
        const uint2* pl = (const uint2*)(flo + (size_t)s * C);
        #pragma unroll
        for (int v = 0; v < V; v++) {
            uint2 hw = ph[lane + 32 * v];
            uint2 lw = pl[lane + 32 * v];
            float2 h0 = __half22float2(*(__half2*)&hw.x);
            float2 h1 = __half22float2(*(__half2*)&hw.y);
            float2 l0 = __half22float2(*(__half2*)&lw.x);
            float2 l1 = __half22float2(*(__half2*)&lw.y);
            acc[v].x += h0.x + l0.x;
            acc[v].y += h0.y + l0.y;
            acc[v].z += h1.x + l1.x;
            acc[v].w += h1.y + l1.y;
        }
    }
    float inv = 1.0f / (float)max(end - beg, 1);
    #pragma unroll
    for (int v = 0; v < V; v++) {
        float4 a = acc[v];
        a.x *= inv; a.y *= inv; a.z *= inv; a.w *= inv;
        __half h0, h1, h2, h3, l0, l1, l2, l3;
        split_f32(a.x, h0, l0); split_f32(a.y, h1, l1);
        split_f32(a.z, h2, l2); split_f32(a.w, h3, l3);
        uint2 hw, lw;
        *(__half2*)&hw.x = __halves2half2(h0, h1);
        *(__half2*)&hw.y = __halves2half2(h2, h3);
        *(__half2*)&lw.x = __halves2half2(l0, l1);
        *(__half2*)&lw.y = __halves2half2(l2, l3);
        ((uint2*)(ahi + (size_t)node * C))[lane + 32 * v] = hw;
        ((uint2*)(alo + (size_t)node * C))[lane + 32 * v] = lw;
    }
}

// ---------------------------------------------------------------------------
// Layer-2 gather (commuted): out[node] += mean over in-edges of y2l[src]
// y2l is fp16, 128 cols. One warp per node, lane = 4 cols (uint2 = 4 halves).
// ---------------------------------------------------------------------------
__global__ void gather_acc_kernel(const __half* __restrict__ y2l,
                                  float* __restrict__ out)
{
    int node = blockIdx.x * (blockDim.x >> 5) + (threadIdx.x >> 5);
    if (node >= N_NODES) return;
    int lane = threadIdx.x & 31;
    int beg = g_row_start[node];
    int end = g_row_start[node + 1];

    float4 acc = make_float4(0.f, 0.f, 0.f, 0.f);
    for (int k = beg; k < end; k++) {
        int s = g_csr_src[k];
        uint2 w = ((const uint2*)(y2l + (size_t)s * OUT_C))[lane];
        float2 v0 = __half22float2(*(__half2*)&w.x);
        float2 v1 = __half22float2(*(__half2*)&w.y);
        acc.x += v0.x; acc.y += v0.y; acc.z += v1.x; acc.w += v1.y;
    }
    float inv = 1.0f / (float)max(end - beg, 1);
    float4* o = (float4*)(out + (size_t)node * OUT_C) + lane;
    float4 p = *o;
    p.x += acc.x * inv; p.y += acc.y * inv;
    p.z += acc.z * inv; p.w += acc.w * inv;
    *o = p;
}

// ---------------------------------------------------------------------------
// Pipelined warp-MMA GEMM, CTA tile 128(M) x 128(N), 8 warps, 2 stages.
// fp16 2-term split: acc = Ah*Bh + Al*Bh  (= A(22-bit) * B(fp16)).
// K_TOT in chunks of 64. HALVES=2: A=[A0|A1]; HALVES=1: A=A0.
// MODE 0 (layer1): h-out = relu(acc + bias) -> split fp16.
// MODE 1 (layer2): cols<128 -> y2l fp16 (no bias); cols>=128 -> out fp32 +bias.
// SMEM per stage: Ahi 16K | Alo 16K | Bh 16K = 48KB; 2 stages = 96KB.
// ---------------------------------------------------------------------------
#define ST_A_HI(s) (smem_raw + (s) * 49152)
#define ST_A_LO(s) (smem_raw + (s) * 49152 + 16384)
#define ST_B_HI(s) (smem_raw + (s) * 49152 + 32768)
#define MMA_SMEM_TOTAL 98304

template<int K_TOT, int HALVES, int N_TOT, int MODE>
__global__ __launch_bounds__(256)
void sage_mma_warp(const __half* __restrict__ A0Hi,
                   const __half* __restrict__ A0Lo,
                   const __half* __restrict__ A1Hi,
                   const __half* __restrict__ A1Lo,
                   const __half* __restrict__ Wt,
                   const float* __restrict__ bias,
                   __half* __restrict__ OutH,     // MODE1: y2l (fp16)
                   float* __restrict__ OutF2,     // MODE1: out (fp32)
                   __half* __restrict__ CoutHi,
                   __half* __restrict__ CoutLo,
                   int M)
{
    extern __shared__ char smem_raw[];
    constexpr int CHUNKS = K_TOT / 64;
    constexpr int K_SRC  = K_TOT / HALVES;

    int tid  = threadIdx.x;
    int wid  = tid >> 5;
    int lane = tid & 31;
    int m0 = blockIdx.x * 128;
    int n0 = blockIdx.y * 128;

    auto load_chunk = [&](int c, int s) {
        uint32_t sa_hi = smem_to_u32(ST_A_HI(s));
        uint32_t sa_lo = smem_to_u32(ST_A_LO(s));
        uint32_t sb_hi = smem_to_u32(ST_B_HI(s));
        int row = tid >> 1;
        int j0  = (tid & 1) * 4;
        {
            bool first_src = (HALVES == 1) || (c < CHUNKS / 2);
            const __half* Ah = first_src ? A0Hi : A1Hi;
            const __half* Al = first_src ? A0Lo : A1Lo;
            int k0 = (first_src ? c : c - CHUNKS / 2) * 64;
            int gm = m0 + row;
            bool valid = gm < M;
            const __half* ph = Ah + (size_t)gm * K_SRC + k0;
            const __half* pl = Al + (size_t)gm * K_SRC + k0;
            #pragma unroll
            for (int j = j0; j < j0 + 4; j++) {
                uint32_t off = SMEM_SWIZZLE_128B((uint32_t)(row * 128 + j * 16));
                cp_async16(sa_hi + off, ph + j * 8, valid);
                cp_async16(sa_lo + off, pl + j * 8, valid);
            }
        }
        {
            int kg = c * 64;
            const __half* bh = Wt + (size_t)(n0 + row) * K_TOT + kg;
            #pragma unroll
            for (int j = j0; j < j0 + 4; j++) {
                uint32_t off = SMEM_SWIZZLE_128B((uint32_t)(row * 128 + j * 16));
                cp_async16(sb_hi + off, bh + j * 8, true);
            }
        }
        CP_COMMIT();
    };

    float acc[16][4];
    #pragma unroll
    for (int nt = 0; nt < 16; nt++)
        #pragma unroll
        for (int q = 0; q < 4; q++) acc[nt][q] = 0.f;

    load_chunk(0, 0);

    for (int c = 0; c < CHUNKS; c++) {
        int s = c & 1;
        if (c + 1 < CHUNKS) {
            load_chunk(c + 1, (c + 1) & 1);
            CP_WAIT(1);
        } else {
            CP_WAIT(0);
        }
        __syncthreads();

        uint32_t sa_hi = smem_to_u32(ST_A_HI(s));
        uint32_t sa_lo = smem_to_u32(ST_A_LO(s));
        uint32_t sb_hi = smem_to_u32(ST_B_HI(s));

        #pragma unroll
        for (int ks = 0; ks < 4; ks++) {
            uint32_t ah[4], al[4];
            {
                int r  = wid * 16 + (lane & 7) + ((lane >> 3) & 1) * 8;
                int cb = ks * 32 + ((lane >> 4) & 1) * 16;
                uint32_t off = SMEM_SWIZZLE_128B((uint32_t)(r * 128 + cb));
                ldsm_x4(ah, sa_hi + off);
                ldsm_x4(al, sa_lo + off);
            }
            #pragma unroll
            for (int half = 0; half < 4; half++) {
                uint32_t bh[2][4];
                #pragma unroll
                for (int q = 0; q < 2; q++) {
                    int nt0 = half * 4 + q * 2;
                    int r  = nt0 * 8 + (lane & 7) + ((lane >> 4) & 1) * 8;
                    int cb = ks * 32 + ((lane >> 3) & 1) * 16;
                    uint32_t off = SMEM_SWIZZLE_128B((uint32_t)(r * 128 + cb));
                    ldsm_x4(bh[q], sb_hi + off);
                }
                #pragma unroll
                for (int q = 0; q < 2; q++)
                    #pragma unroll
                    for (int sub = 0; sub < 2; sub++) {
                        int nt = half * 4 + q * 2 + sub;
                        mma_f16(acc[nt], ah, &bh[q][sub * 2]);
                        mma_f16(acc[nt], al, &bh[q][sub * 2]);
                    }
            }
        }
        __syncthreads();
    }

    // ---- epilogue ----
    int g = lane >> 2;
    int t = lane & 3;
    int r0 = m0 + wid * 16 + g;
    int r1 = r0 + 8;
    #pragma unroll
    for (int nt = 0; nt < 16; nt++) {
        int n = n0 + nt * 8 + 2 * t;
        if (MODE == 0) {
            float2 bb = *(const float2*)(bias + n);
            float c0 = fmaxf(acc[nt][0] + bb.x, 0.f);
            float c1 = fmaxf(acc[nt][1] + bb.y, 0.f);
            float c2 = fmaxf(acc[nt][2] + bb.x, 0.f);
            float c3 = fmaxf(acc[nt][3] + bb.y, 0.f);
            if (r0 < M) {
                __half h0, h1, l0, l1;
                split_f32(c0, h0, l0); split_f32(c1, h1, l1);
                *(__half2*)(CoutHi + (size_t)r0 * N_TOT + n) = __halves2half2(h0, h1);
                *(__half2*)(CoutLo + (size_t)r0 * N_TOT + n) = __halves2half2(l0, l1);
            }
            if (r1 < M) {
                __half h2, h3, l2, l3;
                split_f32(c2, h2, l2); split_f32(c3, h3, l3);
                *(__half2*)(CoutHi + (size_t)r1 * N_TOT + n) = __halves2half2(h2, h3);
                *(__half2*)(CoutLo + (size_t)r1 * N_TOT + n) = __halves2half2(l2, l3);
            }
        } else {
            if (n < 128) {
                if (r0 < M) *(__half2*)(OutH + (size_t)r0 * 128 + n) =
                    __halves2half2(__float2half_rn(acc[nt][0]), __float2half_rn(acc[nt][1]));
                if (r1 < M) *(__half2*)(OutH + (size_t)r1 * 128 + n) =
                    __halves2half2(__float2half_rn(acc[nt][2]), __float2half_rn(acc[nt][3]));
            } else {
                int nn = n - 128;
                float2 bb = *(const float2*)(bias + nn);
                if (r0 < M) *(float2*)(OutF2 + (size_t)r0 * 128 + nn) =
                    make_float2(acc[nt][0] + bb.x, acc[nt][1] + bb.y);
                if (r1 < M) *(float2*)(OutF2 + (size_t)r1 * 128 + nn) =
                    make_float2(acc[nt][2] + bb.x, acc[nt][3] + bb.y);
            }
        }
    }
}

// ---------------------------------------------------------------------------
// Launch
// ---------------------------------------------------------------------------
extern "C" void kernel_launch(void* const* d_in, const int* in_sizes, int n_in,
                              void* d_out, int out_size)
{
    const float* x   = (const float*)d_in[0];
    const int*   ei  = (const int*)d_in[1];     // int32 (JAX x64 disabled)
    const float* W1l = (const float*)d_in[2];
    const float* b1  = (const float*)d_in[3];
    const float* W1r = (const float*)d_in[4];
    const float* W2l = (const float*)d_in[5];
    const float* b2  = (const float*)d_in[6];
    const float* W2r = (const float*)d_in[7];
    float*       out = (float*)d_out;

    const int* src = ei;
    const int* dst = ei + N_EDGES;

    __half *xhi, *xlo, *a1hi, *a1lo, *hhi, *hlo, *wt1, *wt2, *y2l;
    cudaGetSymbolAddress((void**)&y2l,  g_y2l);
    cudaGetSymbolAddress((void**)&xhi,  g_x_hi);
    cudaGetSymbolAddress((void**)&xlo,  g_x_lo);
    cudaGetSymbolAddress((void**)&a1hi, g_a1_hi);
    cudaGetSymbolAddress((void**)&a1lo, g_a1_lo);
    cudaGetSymbolAddress((void**)&hhi,  g_h_hi);
    cudaGetSymbolAddress((void**)&hlo,  g_h_lo);
    cudaGetSymbolAddress((void**)&wt1,  g_wt1);
    cudaGetSymbolAddress((void**)&wt2,  g_wt2);

    auto gemm1 = sage_mma_warp<256, 2, 256, 0>;
    auto gemm2 = sage_mma_warp<256, 1, 256, 1>;
    cudaFuncSetAttribute(gemm1, cudaFuncAttributeMaxDynamicSharedMemorySize, MMA_SMEM_TOTAL);
    cudaFuncSetAttribute(gemm2, cudaFuncAttributeMaxDynamicSharedMemorySize, MMA_SMEM_TOTAL);

    const int NB = (N_NODES + 255) / 256;
    int mgrid = (N_NODES + 127) / 128;

    // ---- CSR build (cnt_int is zero at entry; stage1 re-zeroes it) ----
    hist_kernel<<<(N_EDGES + 255) / 256, 256>>>(dst);
    scan_stage1_kernel<<<NB, 256>>>();
    scan_stage2_kernel<<<1, 256>>>(NB);
    scan_stage3_kernel<<<NB, 256>>>();
    fill_kernel<<<(N_EDGES + 255) / 256, 256>>>(src, dst);

    // ---- feature + weight prep ----
    {
        int n4 = N_NODES * IN_C / 4;
        split_feat_kernel<<<(n4 + 255) / 256, 256>>>(x, xhi, xlo, n4);
    }
    prep_w_kernel<<<(2 * 65536 + 255) / 256, 256>>>(W1l, W1r, W2l, W2r);

    // ---- layer 1: gather x -> a1, then [a1|x] @ wt1 -> h (split fp16) ----
    {
        int warps_per_block = 8;
        int grid = (N_NODES + warps_per_block - 1) / warps_per_block;
        gather_f16_kernel<IN_C><<<grid, warps_per_block * 32>>>(xhi, xlo, a1hi, a1lo);
    }
    {
        dim3 grid(mgrid, 2);
        gemm1<<<grid, 256, MMA_SMEM_TOTAL>>>(
            a1hi, a1lo, xhi, xlo, wt1, b1,
            nullptr, nullptr, hhi, hlo, N_NODES);
    }

    // ---- layer 2 (gather commuted): h @ [W2l|W2r] -> y2l (fp16), out(+b2) ----
    {
        dim3 grid(mgrid, 2);
        gemm2<<<grid, 256, MMA_SMEM_TOTAL>>>(
            hhi, hlo, nullptr, nullptr, wt2, b2,
            y2l, out, nullptr, nullptr, N_NODES);
    }
    // out += mean-gather(y2l)
    {
        int warps_per_block = 8;
        int grid = (N_NODES + warps_per_block - 1) / warps_per_block;
        gather_acc_kernel<<<grid, warps_per_block * 32>>>(y2l, out);
    }
}

// round 15
// speedup vs baseline: 4.7042x; 1.4539x over previous
#include <cuda_runtime.h>
#include <cuda_fp16.h>
#include <cstdint>

// Problem constants (match reference_code)
#define IN_C    128
#define HID_C   256
#define OUT_C   128
#define N_NODES 50000
#define N_EDGES 600000

// ---------------------------------------------------------------------------
// Scratch (no cudaMalloc allowed): device globals
// ---------------------------------------------------------------------------
__device__ int g_cnt_int  [N_NODES];     // zero at entry (restored by scan_stage1)
__device__ int g_row_start[N_NODES + 1];
__device__ int g_cursor   [N_NODES];
__device__ int g_csr_src  [N_EDGES];
__device__ int g_bsum     [256];

// fp16 feature pipeline (single precision piece everywhere)
__device__ __half g_x  [(size_t)N_NODES * IN_C];
__device__ __half g_a1 [(size_t)N_NODES * IN_C];
__device__ __half g_h  [(size_t)N_NODES * HID_C];
__device__ __half g_y2l[(size_t)N_NODES * OUT_C];   // h @ W2l (fp16)

// Pre-truncated transposed weights (fp16):
//  wt1[n][k], n in [0,256), k in [0,256): k<128 -> W1l[k][n], else W1r[k-128][n]
//  wt2[n][k], n in [0,256), k in [0,256): n<128 -> W2l[k][n], else W2r[k][n-128]
__device__ __half g_wt1[HID_C * (2 * IN_C)];
__device__ __half g_wt2[(2 * OUT_C) * HID_C];

// ---------------------------------------------------------------------------
// Helpers
// ---------------------------------------------------------------------------
__device__ __forceinline__ uint32_t smem_to_u32(const void* p) {
    uint32_t a;
    asm("{ .reg .u64 t; cvta.to.shared.u64 t, %1; cvt.u32.u64 %0, t; }" : "=r"(a) : "l"(p));
    return a;
}

#define SMEM_SWIZZLE_128B(off) ((off) ^ (((off) >> 3) & 0x70))

__device__ __forceinline__ void ldsm_x4(uint32_t* r, uint32_t addr) {
    asm volatile("ldmatrix.sync.aligned.m8n8.x4.shared.b16 {%0,%1,%2,%3}, [%4];"
        : "=r"(r[0]), "=r"(r[1]), "=r"(r[2]), "=r"(r[3]) : "r"(addr));
}

__device__ __forceinline__ void mma_f16(float* c, const uint32_t* a, const uint32_t* b) {
    asm volatile("mma.sync.aligned.m16n8k16.row.col.f32.f16.f16.f32 "
        "{%0,%1,%2,%3}, {%4,%5,%6,%7}, {%8,%9}, {%0,%1,%2,%3};"
        : "+f"(c[0]), "+f"(c[1]), "+f"(c[2]), "+f"(c[3])
        : "r"(a[0]), "r"(a[1]), "r"(a[2]), "r"(a[3]), "r"(b[0]), "r"(b[1]));
}

__device__ __forceinline__ void cp_async16(uint32_t smem, const void* g, bool valid) {
    int sz = valid ? 16 : 0;
    asm volatile("cp.async.cg.shared.global [%0], [%1], 16, %2;"
        :: "r"(smem), "l"(g), "r"(sz) : "memory");
}
#define CP_COMMIT() asm volatile("cp.async.commit_group;" ::: "memory")
#define CP_WAIT(n)  asm volatile("cp.async.wait_group %0;" :: "n"(n) : "memory")

// ---------------------------------------------------------------------------
// CSR build
// ---------------------------------------------------------------------------
__global__ void hist_kernel(const int* __restrict__ dst)
{
    int e = blockIdx.x * blockDim.x + threadIdx.x;
    if (e < N_EDGES) atomicAdd(&g_cnt_int[dst[e]], 1);
}

// Stage 1: per-block exclusive scan + block sum; re-zeroes cnt_int after read
// (restores the "zero at entry" invariant for the next graph replay).
__global__ void scan_stage1_kernel()
{
    __shared__ int sdata[256];
    int tid = threadIdx.x;
    int i = blockIdx.x * 256 + tid;
    int v = (i < N_NODES) ? g_cnt_int[i] : 0;
    if (i < N_NODES) g_cnt_int[i] = 0;
    sdata[tid] = v;
    __syncthreads();
    #pragma unroll
    for (int s = 1; s < 256; s <<= 1) {
        int t = (tid >= s) ? sdata[tid - s] : 0;
        __syncthreads();
        sdata[tid] += t;
        __syncthreads();
    }
    if (i < N_NODES) g_row_start[i] = sdata[tid] - v;
    if (tid == 255) g_bsum[blockIdx.x] = sdata[255];
}

__global__ void scan_stage2_kernel(int nblocks)
{
    __shared__ int sdata[256];
    int tid = threadIdx.x;
    int v = (tid < nblocks) ? g_bsum[tid] : 0;
    sdata[tid] = v;
    __syncthreads();
    #pragma unroll
    for (int s = 1; s < 256; s <<= 1) {
        int t = (tid >= s) ? sdata[tid - s] : 0;
        __syncthreads();
        sdata[tid] += t;
        __syncthreads();
    }
    if (tid < nblocks) g_bsum[tid] = sdata[tid] - v;
    if (tid == 255) g_row_start[N_NODES] = sdata[255];
}

__global__ void scan_stage3_kernel()
{
    int i = blockIdx.x * blockDim.x + threadIdx.x;
    if (i < N_NODES) {
        int rs = g_row_start[i] + g_bsum[blockIdx.x];
        g_row_start[i] = rs;
        g_cursor[i]    = rs;
    }
}

__global__ void fill_kernel(const int* __restrict__ src, const int* __restrict__ dst)
{
    int e = blockIdx.x * blockDim.x + threadIdx.x;
    if (e < N_EDGES) {
        int pos = atomicAdd(&g_cursor[dst[e]], 1);
        g_csr_src[pos] = src[e];
    }
}

// ---------------------------------------------------------------------------
// Convert fp32 features -> fp16
// ---------------------------------------------------------------------------
__global__ void cvt_feat_kernel(const float* __restrict__ in,
                                __half* __restrict__ o, int n4)
{
    int i = blockIdx.x * blockDim.x + threadIdx.x;
    if (i >= n4) return;
    float4 v = *(const float4*)(in + i * 4);
    __half2* p = (__half2*)(o + i * 4);
    p[0] = __halves2half2(__float2half_rn(v.x), __float2half_rn(v.y));
    p[1] = __halves2half2(__float2half_rn(v.z), __float2half_rn(v.w));
}

// ---------------------------------------------------------------------------
// Combined weight prep (both layers in one launch)
// ---------------------------------------------------------------------------
__global__ void prep_w_kernel(const float* __restrict__ W1l,
                              const float* __restrict__ W1r,
                              const float* __restrict__ W2l,
                              const float* __restrict__ W2r)
{
    int idx = blockIdx.x * blockDim.x + threadIdx.x;
    const int T1 = HID_C * 256;        // 65536
    if (idx < T1) {
        int n = idx / 256;
        int k = idx % 256;
        float v = (k < 128) ? W1l[(size_t)k * HID_C + n]
                            : W1r[(size_t)(k - 128) * HID_C + n];
        g_wt1[idx] = __float2half_rn(v);
    } else {
        idx -= T1;
        if (idx >= 256 * HID_C) return;
        int n = idx / HID_C;           // 0..255 output col (0-127 y2l, 128-255 y2r)
        int k = idx % HID_C;
        float v = (n < 128) ? W2l[(size_t)k * OUT_C + n]
                            : W2r[(size_t)k * OUT_C + (n - 128)];
        g_wt2[idx] = __float2half_rn(v);
    }
}

// ---------------------------------------------------------------------------
// Gather-aggregate (layer 1): fp16 in, fp32 accumulate, fp16 mean out
// ---------------------------------------------------------------------------
template<int C>
__global__ void gather_f16_kernel(const __half* __restrict__ f,
                                  __half* __restrict__ a)
{
    int node = blockIdx.x * (blockDim.x >> 5) + (threadIdx.x >> 5);
    if (node >= N_NODES) return;
    int lane = threadIdx.x & 31;
    int beg = g_row_start[node];
    int end = g_row_start[node + 1];

    constexpr int V = C / 128;
    float4 acc[V];
    #pragma unroll
    for (int v = 0; v < V; v++) acc[v] = make_float4(0.f, 0.f, 0.f, 0.f);

    for (int k = beg; k < end; k++) {
        int s = g_csr_src[k];
        const uint2* p = (const uint2*)(f + (size_t)s * C);
        #pragma unroll
        for (int v = 0; v < V; v++) {
            uint2 w = p[lane + 32 * v];
            float2 v0 = __half22float2(*(__half2*)&w.x);
            float2 v1 = __half22float2(*(__half2*)&w.y);
            acc[v].x += v0.x; acc[v].y += v0.y;
            acc[v].z += v1.x; acc[v].w += v1.y;
        }
    }
    float inv = 1.0f / (float)max(end - beg, 1);
    #pragma unroll
    for (int v = 0; v < V; v++) {
        uint2 w;
        *(__half2*)&w.x = __halves2half2(__float2half_rn(acc[v].x * inv),
                                         __float2half_rn(acc[v].y * inv));
        *(__half2*)&w.y = __halves2half2(__float2half_rn(acc[v].z * inv),
                                         __float2half_rn(acc[v].w * inv));
        ((uint2*)(a + (size_t)node * C))[lane + 32 * v] = w;
    }
}

// ---------------------------------------------------------------------------
// Layer-2 gather (commuted): out[node] += mean over in-edges of y2l[src]
// ---------------------------------------------------------------------------
__global__ void gather_acc_kernel(const __half* __restrict__ y2l,
                                  float* __restrict__ out)
{
    int node = blockIdx.x * (blockDim.x >> 5) + (threadIdx.x >> 5);
    if (node >= N_NODES) return;
    int lane = threadIdx.x & 31;
    int beg = g_row_start[node];
    int end = g_row_start[node + 1];

    float4 acc = make_float4(0.f, 0.f, 0.f, 0.f);
    for (int k = beg; k < end; k++) {
        int s = g_csr_src[k];
        uint2 w = ((const uint2*)(y2l + (size_t)s * OUT_C))[lane];
        float2 v0 = __half22float2(*(__half2*)&w.x);
        float2 v1 = __half22float2(*(__half2*)&w.y);
        acc.x += v0.x; acc.y += v0.y; acc.z += v1.x; acc.w += v1.y;
    }
    float inv = 1.0f / (float)max(end - beg, 1);
    float4* o = (float4*)(out + (size_t)node * OUT_C) + lane;
    float4 p = *o;
    p.x += acc.x * inv; p.y += acc.y * inv;
    p.z += acc.z * inv; p.w += acc.w * inv;
    *o = p;
}

// ---------------------------------------------------------------------------
// Pipelined warp-MMA GEMM, CTA tile 128(M) x 128(N), 8 warps, 2 stages.
// Pure fp16 x fp16, fp32 accumulators: 1 MMA per (k16, n8) step.
// K_TOT in chunks of 64. HALVES=2: A=[A0|A1]; HALVES=1: A=A0.
// MODE 0 (layer1): h = relu(acc + bias) -> fp16.
// MODE 1 (layer2): cols<128 -> y2l fp16 (no bias); cols>=128 -> out fp32 +bias.
// SMEM per stage: A 16K | B 16K = 32KB; 2 stages = 64KB.
// ---------------------------------------------------------------------------
#define ST_A(s) (smem_raw + (s) * 32768)
#define ST_B(s) (smem_raw + (s) * 32768 + 16384)
#define MMA_SMEM_TOTAL 65536

template<int K_TOT, int HALVES, int N_TOT, int MODE>
__global__ __launch_bounds__(256)
void sage_mma_warp(const __half* __restrict__ A0,
                   const __half* __restrict__ A1,
                   const __half* __restrict__ Wt,
                   const float* __restrict__ bias,
                   __half* __restrict__ OutH,     // MODE1: y2l (fp16)
                   float* __restrict__ OutF2,     // MODE1: out (fp32)
                   __half* __restrict__ Cout,     // MODE0: h (fp16)
                   int M)
{
    extern __shared__ char smem_raw[];
    constexpr int CHUNKS = K_TOT / 64;
    constexpr int K_SRC  = K_TOT / HALVES;

    int tid  = threadIdx.x;
    int wid  = tid >> 5;
    int lane = tid & 31;
    int m0 = blockIdx.x * 128;
    int n0 = blockIdx.y * 128;

    auto load_chunk = [&](int c, int s) {
        uint32_t sa = smem_to_u32(ST_A(s));
        uint32_t sb = smem_to_u32(ST_B(s));
        int row = tid >> 1;
        int j0  = (tid & 1) * 4;
        {
            bool first_src = (HALVES == 1) || (c < CHUNKS / 2);
            const __half* A = first_src ? A0 : A1;
            int k0 = (first_src ? c : c - CHUNKS / 2) * 64;
            int gm = m0 + row;
            bool valid = gm < M;
            const __half* p = A + (size_t)gm * K_SRC + k0;
            #pragma unroll
            for (int j = j0; j < j0 + 4; j++) {
                uint32_t off = SMEM_SWIZZLE_128B((uint32_t)(row * 128 + j * 16));
                cp_async16(sa + off, p + j * 8, valid);
            }
        }
        {
            int kg = c * 64;
            const __half* b = Wt + (size_t)(n0 + row) * K_TOT + kg;
            #pragma unroll
            for (int j = j0; j < j0 + 4; j++) {
                uint32_t off = SMEM_SWIZZLE_128B((uint32_t)(row * 128 + j * 16));
                cp_async16(sb + off, b + j * 8, true);
            }
        }
        CP_COMMIT();
    };

    float acc[16][4];
    #pragma unroll
    for (int nt = 0; nt < 16; nt++)
        #pragma unroll
        for (int q = 0; q < 4; q++) acc[nt][q] = 0.f;

    load_chunk(0, 0);

    for (int c = 0; c < CHUNKS; c++) {
        int s = c & 1;
        if (c + 1 < CHUNKS) {
            load_chunk(c + 1, (c + 1) & 1);
            CP_WAIT(1);
        } else {
            CP_WAIT(0);
        }
        __syncthreads();

        uint32_t sa = smem_to_u32(ST_A(s));
        uint32_t sb = smem_to_u32(ST_B(s));

        #pragma unroll
        for (int ks = 0; ks < 4; ks++) {
            uint32_t ah[4];
            {
                int r  = wid * 16 + (lane & 7) + ((lane >> 3) & 1) * 8;
                int cb = ks * 32 + ((lane >> 4) & 1) * 16;
                uint32_t off = SMEM_SWIZZLE_128B((uint32_t)(r * 128 + cb));
                ldsm_x4(ah, sa + off);
            }
            #pragma unroll
            for (int half = 0; half < 4; half++) {
                uint32_t bh[2][4];
                #pragma unroll
                for (int q = 0; q < 2; q++) {
                    int nt0 = half * 4 + q * 2;
                    int r  = nt0 * 8 + (lane & 7) + ((lane >> 4) & 1) * 8;
                    int cb = ks * 32 + ((lane >> 3) & 1) * 16;
                    uint32_t off = SMEM_SWIZZLE_128B((uint32_t)(r * 128 + cb));
                    ldsm_x4(bh[q], sb + off);
                }
                #pragma unroll
                for (int q = 0; q < 2; q++)
                    #pragma unroll
                    for (int sub = 0; sub < 2; sub++) {
                        int nt = half * 4 + q * 2 + sub;
                        mma_f16(acc[nt], ah, &bh[q][sub * 2]);
                    }
            }
        }
        __syncthreads();
    }

    // ---- epilogue ----
    int g = lane >> 2;
    int t = lane & 3;
    int r0 = m0 + wid * 16 + g;
    int r1 = r0 + 8;
    #pragma unroll
    for (int nt = 0; nt < 16; nt++) {
        int n = n0 + nt * 8 + 2 * t;
        if (MODE == 0) {
            float2 bb = *(const float2*)(bias + n);
            float c0 = fmaxf(acc[nt][0] + bb.x, 0.f);
            float c1 = fmaxf(acc[nt][1] + bb.y, 0.f);
            float c2 = fmaxf(acc[nt][2] + bb.x, 0.f);
            float c3 = fmaxf(acc[nt][3] + bb.y, 0.f);
            if (r0 < M) *(__half2*)(Cout + (size_t)r0 * N_TOT + n) =
                __halves2half2(__float2half_rn(c0), __float2half_rn(c1));
            if (r1 < M) *(__half2*)(Cout + (size_t)r1 * N_TOT + n) =
                __halves2half2(__float2half_rn(c2), __float2half_rn(c3));
        } else {
            if (n < 128) {
                if (r0 < M) *(__half2*)(OutH + (size_t)r0 * 128 + n) =
                    __halves2half2(__float2half_rn(acc[nt][0]), __float2half_rn(acc[nt][1]));
                if (r1 < M) *(__half2*)(OutH + (size_t)r1 * 128 + n) =
                    __halves2half2(__float2half_rn(acc[nt][2]), __float2half_rn(acc[nt][3]));
            } else {
                int nn = n - 128;
                float2 bb = *(const float2*)(bias + nn);
                if (r0 < M) *(float2*)(OutF2 + (size_t)r0 * 128 + nn) =
                    make_float2(acc[nt][0] + bb.x, acc[nt][1] + bb.y);
                if (r1 < M) *(float2*)(OutF2 + (size_t)r1 * 128 + nn) =
                    make_float2(acc[nt][2] + bb.x, acc[nt][3] + bb.y);
            }
        }
    }
}

// ---------------------------------------------------------------------------
// Launch
// ---------------------------------------------------------------------------
extern "C" void kernel_launch(void* const* d_in, const int* in_sizes, int n_in,
                              void* d_out, int out_size)
{
    const float* x   = (const float*)d_in[0];
    const int*   ei  = (const int*)d_in[1];     // int32 (JAX x64 disabled)
    const float* W1l = (const float*)d_in[2];
    const float* b1  = (const float*)d_in[3];
    const float* W1r = (const float*)d_in[4];
    const float* W2l = (const float*)d_in[5];
    const float* b2  = (const float*)d_in[6];
    const float* W2r = (const float*)d_in[7];
    float*       out = (float*)d_out;

    const int* src = ei;
    const int* dst = ei + N_EDGES;

    __half *xh, *a1, *h, *wt1, *wt2, *y2l;
    cudaGetSymbolAddress((void**)&y2l, g_y2l);
    cudaGetSymbolAddress((void**)&xh,  g_x);
    cudaGetSymbolAddress((void**)&a1,  g_a1);
    cudaGetSymbolAddress((void**)&h,   g_h);
    cudaGetSymbolAddress((void**)&wt1, g_wt1);
    cudaGetSymbolAddress((void**)&wt2, g_wt2);

    auto gemm1 = sage_mma_warp<256, 2, 256, 0>;
    auto gemm2 = sage_mma_warp<256, 1, 256, 1>;
    cudaFuncSetAttribute(gemm1, cudaFuncAttributeMaxDynamicSharedMemorySize, MMA_SMEM_TOTAL);
    cudaFuncSetAttribute(gemm2, cudaFuncAttributeMaxDynamicSharedMemorySize, MMA_SMEM_TOTAL);

    const int NB = (N_NODES + 255) / 256;
    int mgrid = (N_NODES + 127) / 128;

    // ---- CSR build (cnt_int is zero at entry; stage1 re-zeroes it) ----
    hist_kernel<<<(N_EDGES + 255) / 256, 256>>>(dst);
    scan_stage1_kernel<<<NB, 256>>>();
    scan_stage2_kernel<<<1, 256>>>(NB);
    scan_stage3_kernel<<<NB, 256>>>();
    fill_kernel<<<(N_EDGES + 255) / 256, 256>>>(src, dst);

    // ---- feature + weight prep ----
    {
        int n4 = N_NODES * IN_C / 4;
        cvt_feat_kernel<<<(n4 + 255) / 256, 256>>>(x, xh, n4);
    }
    prep_w_kernel<<<(2 * 65536 + 255) / 256, 256>>>(W1l, W1r, W2l, W2r);

    // ---- layer 1: gather x -> a1, then [a1|x] @ wt1 -> h (fp16) ----
    {
        int warps_per_block = 8;
        int grid = (N_NODES + warps_per_block - 1) / warps_per_block;
        gather_f16_kernel<IN_C><<<grid, warps_per_block * 32>>>(xh, a1);
    }
    {
        dim3 grid(mgrid, 2);
        gemm1<<<grid, 256, MMA_SMEM_TOTAL>>>(
            a1, xh, wt1, b1, nullptr, nullptr, h, N_NODES);
    }

    // ---- layer 2 (gather commuted): h @ [W2l|W2r] -> y2l (fp16), out(+b2) ----
    {
        dim3 grid(mgrid, 2);
        gemm2<<<grid, 256, MMA_SMEM_TOTAL>>>(
            h, nullptr, wt2, b2, y2l, out, nullptr, N_NODES);
    }
    // out += mean-gather(y2l)
    {
        int warps_per_block = 8;
        int grid = (N_NODES + warps_per_block - 1) / warps_per_block;
        gather_acc_kernel<<<grid, warps_per_block * 32>>>(y2l, out);
    }
}

// round 16
// speedup vs baseline: 5.1234x; 1.0891x over previous
#include <cuda_runtime.h>
#include <cuda_fp16.h>
#include <cstdint>

// Problem constants (match reference_code)
#define IN_C    128
#define HID_C   256
#define OUT_C   128
#define N_NODES 50000
#define N_EDGES 600000
#define NB_SCAN 196              // ceil(N_NODES / 256)

// ---------------------------------------------------------------------------
// Scratch (no cudaMalloc allowed): device globals
// ---------------------------------------------------------------------------
__device__ int g_cnt_int  [N_NODES];     // zero at entry (restored by scan_stage1)
__device__ int g_row_start[N_NODES + 1];
__device__ int g_cursor   [N_NODES];
__device__ int g_csr_src  [N_EDGES];
__device__ int g_bsum     [256];

// fp16 feature pipeline
__device__ __half g_x  [(size_t)N_NODES * IN_C];
__device__ __half g_a1 [(size_t)N_NODES * IN_C];
__device__ __half g_h  [(size_t)N_NODES * HID_C];
__device__ __half g_y2l[(size_t)N_NODES * OUT_C];   // h @ W2l (fp16)

// Pre-truncated transposed weights (fp16):
//  wt1[n][k], n in [0,256), k in [0,256): k<128 -> W1l[k][n], else W1r[k-128][n]
//  wt2[n][k], n in [0,256), k in [0,256): n<128 -> W2l[k][n], else W2r[k][n-128]
__device__ __half g_wt1[HID_C * (2 * IN_C)];
__device__ __half g_wt2[(2 * OUT_C) * HID_C];

// ---------------------------------------------------------------------------
// Helpers
// ---------------------------------------------------------------------------
__device__ __forceinline__ uint32_t smem_to_u32(const void* p) {
    uint32_t a;
    asm("{ .reg .u64 t; cvta.to.shared.u64 t, %1; cvt.u32.u64 %0, t; }" : "=r"(a) : "l"(p));
    return a;
}

#define SMEM_SWIZZLE_128B(off) ((off) ^ (((off) >> 3) & 0x70))

__device__ __forceinline__ void ldsm_x4(uint32_t* r, uint32_t addr) {
    asm volatile("ldmatrix.sync.aligned.m8n8.x4.shared.b16 {%0,%1,%2,%3}, [%4];"
        : "=r"(r[0]), "=r"(r[1]), "=r"(r[2]), "=r"(r[3]) : "r"(addr));
}

__device__ __forceinline__ void mma_f16(float* c, const uint32_t* a, const uint32_t* b) {
    asm volatile("mma.sync.aligned.m16n8k16.row.col.f32.f16.f16.f32 "
        "{%0,%1,%2,%3}, {%4,%5,%6,%7}, {%8,%9}, {%0,%1,%2,%3};"
        : "+f"(c[0]), "+f"(c[1]), "+f"(c[2]), "+f"(c[3])
        : "r"(a[0]), "r"(a[1]), "r"(a[2]), "r"(a[3]), "r"(b[0]), "r"(b[1]));
}

__device__ __forceinline__ void cp_async16(uint32_t smem, const void* g, bool valid) {
    int sz = valid ? 16 : 0;
    asm volatile("cp.async.cg.shared.global [%0], [%1], 16, %2;"
        :: "r"(smem), "l"(g), "r"(sz) : "memory");
}
#define CP_COMMIT() asm volatile("cp.async.commit_group;" ::: "memory")
#define CP_WAIT(n)  asm volatile("cp.async.wait_group %0;" :: "n"(n) : "memory")

// ---------------------------------------------------------------------------
// Merged prologue: hist (edges) + feature fp32->fp16 + weight prep, one launch.
// Ranges: [0, E) hist | [E, E + n4) cvt | [E + n4, E + n4 + 2*65536) weights
// ---------------------------------------------------------------------------
#define CVT_N4   (N_NODES * IN_C / 4)
#define PREP_N   (2 * 65536)
#define PRO_TOT  (N_EDGES + CVT_N4 + PREP_N)

__global__ void prologue_kernel(const int* __restrict__ dst,
                                const float* __restrict__ x,
                                const float* __restrict__ W1l,
                                const float* __restrict__ W1r,
                                const float* __restrict__ W2l,
                                const float* __restrict__ W2r)
{
    int gi = blockIdx.x * blockDim.x + threadIdx.x;
    if (gi < N_EDGES) {
        atomicAdd(&g_cnt_int[dst[gi]], 1);
        return;
    }
    gi -= N_EDGES;
    if (gi < CVT_N4) {
        float4 v = *(const float4*)(x + gi * 4);
        __half2* p = (__half2*)(g_x + (size_t)gi * 4);
        p[0] = __halves2half2(__float2half_rn(v.x), __float2half_rn(v.y));
        p[1] = __halves2half2(__float2half_rn(v.z), __float2half_rn(v.w));
        return;
    }
    gi -= CVT_N4;
    if (gi >= PREP_N) return;
    const int T1 = HID_C * 256;        // 65536
    if (gi < T1) {
        int n = gi / 256;
        int k = gi % 256;
        float v = (k < 128) ? W1l[(size_t)k * HID_C + n]
                            : W1r[(size_t)(k - 128) * HID_C + n];
        g_wt1[gi] = __float2half_rn(v);
    } else {
        int idx = gi - T1;
        int n = idx / HID_C;
        int k = idx % HID_C;
        float v = (n < 128) ? W2l[(size_t)k * OUT_C + n]
                            : W2r[(size_t)k * OUT_C + (n - 128)];
        g_wt2[idx] = __float2half_rn(v);
    }
}

// ---------------------------------------------------------------------------
// CSR scan stage 1: per-block exclusive scan + block sum; re-zeroes cnt_int.
// ---------------------------------------------------------------------------
__global__ void scan_stage1_kernel()
{
    __shared__ int sdata[256];
    int tid = threadIdx.x;
    int i = blockIdx.x * 256 + tid;
    int v = (i < N_NODES) ? g_cnt_int[i] : 0;
    if (i < N_NODES) g_cnt_int[i] = 0;
    sdata[tid] = v;
    __syncthreads();
    #pragma unroll
    for (int s = 1; s < 256; s <<= 1) {
        int t = (tid >= s) ? sdata[tid - s] : 0;
        __syncthreads();
        sdata[tid] += t;
        __syncthreads();
    }
    if (i < N_NODES) g_row_start[i] = sdata[tid] - v;
    if (tid == 255) g_bsum[blockIdx.x] = sdata[255];
}

// Stage 3 (fused): every block redundantly scans g_bsum (NB_SCAN entries) in
// SMEM, picks its own exclusive offset, applies it, and inits cursors.
__global__ void scan_stage3_kernel()
{
    __shared__ int sdata[256];
    __shared__ int s_off;
    int tid = threadIdx.x;
    int v = (tid < NB_SCAN) ? g_bsum[tid] : 0;
    sdata[tid] = v;
    __syncthreads();
    #pragma unroll
    for (int s = 1; s < 256; s <<= 1) {
        int t = (tid >= s) ? sdata[tid - s] : 0;
        __syncthreads();
        sdata[tid] += t;
        __syncthreads();
    }
    if (tid == (int)blockIdx.x) s_off = sdata[tid] - v;   // exclusive at blockIdx
    if (blockIdx.x == 0 && tid == 0) g_row_start[N_NODES] = sdata[NB_SCAN - 1];
    __syncthreads();
    int i = blockIdx.x * 256 + tid;
    if (i < N_NODES) {
        int rs = g_row_start[i] + s_off;
        g_row_start[i] = rs;
        g_cursor[i]    = rs;
    }
}

__global__ void fill_kernel(const int* __restrict__ src, const int* __restrict__ dst)
{
    int e = blockIdx.x * blockDim.x + threadIdx.x;
    if (e < N_EDGES) {
        int pos = atomicAdd(&g_cursor[dst[e]], 1);
        g_csr_src[pos] = src[e];
    }
}

// ---------------------------------------------------------------------------
// Gather-aggregate (layer 1): fp16 in, fp32 accumulate, fp16 mean out
// ---------------------------------------------------------------------------
template<int C>
__global__ void gather_f16_kernel(const __half* __restrict__ f,
                                  __half* __restrict__ a)
{
    int node = blockIdx.x * (blockDim.x >> 5) + (threadIdx.x >> 5);
    if (node >= N_NODES) return;
    int lane = threadIdx.x & 31;
    int beg = g_row_start[node];
    int end = g_row_start[node + 1];

    constexpr int V = C / 128;
    float4 acc[V];
    #pragma unroll
    for (int v = 0; v < V; v++) acc[v] = make_float4(0.f, 0.f, 0.f, 0.f);

    for (int k = beg; k < end; k++) {
        int s = g_csr_src[k];
        const uint2* p = (const uint2*)(f + (size_t)s * C);
        #pragma unroll
        for (int v = 0; v < V; v++) {
            uint2 w = p[lane + 32 * v];
            float2 v0 = __half22float2(*(__half2*)&w.x);
            float2 v1 = __half22float2(*(__half2*)&w.y);
            acc[v].x += v0.x; acc[v].y += v0.y;
            acc[v].z += v1.x; acc[v].w += v1.y;
        }
    }
    float inv = 1.0f / (float)max(end - beg, 1);
    #pragma unroll
    for (int v = 0; v < V; v++) {
        uint2 w;
        *(__half2*)&w.x = __halves2half2(__float2half_rn(acc[v].x * inv),
                                         __float2half_rn(acc[v].y * inv));
        *(__half2*)&w.y = __halves2half2(__float2half_rn(acc[v].z * inv),
                                         __float2half_rn(acc[v].w * inv));
        ((uint2*)(a + (size_t)node * C))[lane + 32 * v] = w;
    }
}

// ---------------------------------------------------------------------------
// Layer-2 gather (commuted): out[node] += mean over in-edges of y2l[src]
// ---------------------------------------------------------------------------
__global__ void gather_acc_kernel(const __half* __restrict__ y2l,
                                  float* __restrict__ out)
{
    int node = blockIdx.x * (blockDim.x >> 5) + (threadIdx.x >> 5);
    if (node >= N_NODES) return;
    int lane = threadIdx.x & 31;
    int beg = g_row_start[node];
    int end = g_row_start[node + 1];

    float4 acc = make_float4(0.f, 0.f, 0.f, 0.f);
    for (int k = beg; k < end; k++) {
        int s = g_csr_src[k];
        uint2 w = ((const uint2*)(y2l + (size_t)s * OUT_C))[lane];
        float2 v0 = __half22float2(*(__half2*)&w.x);
        float2 v1 = __half22float2(*(__half2*)&w.y);
        acc.x += v0.x; acc.y += v0.y; acc.z += v1.x; acc.w += v1.y;
    }
    float inv = 1.0f / (float)max(end - beg, 1);
    float4* o = (float4*)(out + (size_t)node * OUT_C) + lane;
    float4 p = *o;
    p.x += acc.x * inv; p.y += acc.y * inv;
    p.z += acc.z * inv; p.w += acc.w * inv;
    *o = p;
}

// ---------------------------------------------------------------------------
// Pipelined warp-MMA GEMM, CTA tile 128(M) x 128(N), 8 warps, 2 stages.
// Warp tile 32(M) x 64(N): wm = wid & 3 (m band), wn = wid >> 2 (n half).
// Pure fp16 x fp16, fp32 accumulators: 1 MMA per (k16, n8) step.
// K_TOT in chunks of 64. HALVES=2: A=[A0|A1]; HALVES=1: A=A0.
// MODE 0 (layer1): h = relu(acc + bias) -> fp16.
// MODE 1 (layer2): cols<128 -> y2l fp16 (no bias); cols>=128 -> out fp32 +bias.
// SMEM per stage: A 16K | B 16K = 32KB; 2 stages = 64KB.
// ---------------------------------------------------------------------------
#define ST_A(s) (smem_raw + (s) * 32768)
#define ST_B(s) (smem_raw + (s) * 32768 + 16384)
#define MMA_SMEM_TOTAL 65536

template<int K_TOT, int HALVES, int N_TOT, int MODE>
__global__ __launch_bounds__(256)
void sage_mma_warp(const __half* __restrict__ A0,
                   const __half* __restrict__ A1,
                   const __half* __restrict__ Wt,
                   const float* __restrict__ bias,
                   __half* __restrict__ OutH,     // MODE1: y2l (fp16)
                   float* __restrict__ OutF2,     // MODE1: out (fp32)
                   __half* __restrict__ Cout,     // MODE0: h (fp16)
                   int M)
{
    extern __shared__ char smem_raw[];
    constexpr int CHUNKS = K_TOT / 64;
    constexpr int K_SRC  = K_TOT / HALVES;

    int tid  = threadIdx.x;
    int wid  = tid >> 5;
    int lane = tid & 31;
    int wm   = wid & 3;           // m band (x32)
    int wn   = wid >> 2;          // n half (x64)
    int m0 = blockIdx.x * 128;
    int n0 = blockIdx.y * 128;

    auto load_chunk = [&](int c, int s) {
        uint32_t sa = smem_to_u32(ST_A(s));
        uint32_t sb = smem_to_u32(ST_B(s));
        int row = tid >> 1;
        int j0  = (tid & 1) * 4;
        {
            bool first_src = (HALVES == 1) || (c < CHUNKS / 2);
            const __half* A = first_src ? A0 : A1;
            int k0 = (first_src ? c : c - CHUNKS / 2) * 64;
            int gm = m0 + row;
            bool valid = gm < M;
            const __half* p = A + (size_t)gm * K_SRC + k0;
            #pragma unroll
            for (int j = j0; j < j0 + 4; j++) {
                uint32_t off = SMEM_SWIZZLE_128B((uint32_t)(row * 128 + j * 16));
                cp_async16(sa + off, p + j * 8, valid);
            }
        }
        {
            int kg = c * 64;
            const __half* b = Wt + (size_t)(n0 + row) * K_TOT + kg;
            #pragma unroll
            for (int j = j0; j < j0 + 4; j++) {
                uint32_t off = SMEM_SWIZZLE_128B((uint32_t)(row * 128 + j * 16));
                cp_async16(sb + off, b + j * 8, true);
            }
        }
        CP_COMMIT();
    };

    float acc[2][8][4];
    #pragma unroll
    for (int mt = 0; mt < 2; mt++)
        #pragma unroll
        for (int nt = 0; nt < 8; nt++)
            #pragma unroll
            for (int q = 0; q < 4; q++) acc[mt][nt][q] = 0.f;

    load_chunk(0, 0);

    for (int c = 0; c < CHUNKS; c++) {
        int s = c & 1;
        if (c + 1 < CHUNKS) {
            load_chunk(c + 1, (c + 1) & 1);
            CP_WAIT(1);
        } else {
            CP_WAIT(0);
        }
        __syncthreads();

        uint32_t sa = smem_to_u32(ST_A(s));
        uint32_t sb = smem_to_u32(ST_B(s));

        #pragma unroll
        for (int ks = 0; ks < 4; ks++) {
            uint32_t ah[2][4];
            #pragma unroll
            for (int mt = 0; mt < 2; mt++) {
                int r  = wm * 32 + mt * 16 + (lane & 7) + ((lane >> 3) & 1) * 8;
                int cb = ks * 32 + ((lane >> 4) & 1) * 16;
                uint32_t off = SMEM_SWIZZLE_128B((uint32_t)(r * 128 + cb));
                ldsm_x4(ah[mt], sa + off);
            }
            #pragma unroll
            for (int grp = 0; grp < 2; grp++) {
                uint32_t bh[2][4];
                #pragma unroll
                for (int q = 0; q < 2; q++) {
                    int nt0 = grp * 4 + q * 2;
                    int r  = wn * 64 + nt0 * 8 + (lane & 7) + ((lane >> 4) & 1) * 8;
                    int cb = ks * 32 + ((lane >> 3) & 1) * 16;
                    uint32_t off = SMEM_SWIZZLE_128B((uint32_t)(r * 128 + cb));
                    ldsm_x4(bh[q], sb + off);
                }
                #pragma unroll
                for (int mt = 0; mt < 2; mt++)
                    #pragma unroll
                    for (int q = 0; q < 2; q++)
                        #pragma unroll
                        for (int sub = 0; sub < 2; sub++) {
                            int nt = grp * 4 + q * 2 + sub;
                            mma_f16(acc[mt][nt], ah[mt], &bh[q][sub * 2]);
                        }
            }
        }
        __syncthreads();
    }

    // ---- epilogue ----
    int g = lane >> 2;
    int t = lane & 3;
    #pragma unroll
    for (int mt = 0; mt < 2; mt++) {
        int r0 = m0 + wm * 32 + mt * 16 + g;
        int r1 = r0 + 8;
        #pragma unroll
        for (int nt = 0; nt < 8; nt++) {
            int n = n0 + wn * 64 + nt * 8 + 2 * t;
            float* a = acc[mt][nt];
            if (MODE == 0) {
                float2 bb = *(const float2*)(bias + n);
                float c0 = fmaxf(a[0] + bb.x, 0.f);
                float c1 = fmaxf(a[1] + bb.y, 0.f);
                float c2 = fmaxf(a[2] + bb.x, 0.f);
                float c3 = fmaxf(a[3] + bb.y, 0.f);
                if (r0 < M) *(__half2*)(Cout + (size_t)r0 * N_TOT + n) =
                    __halves2half2(__float2half_rn(c0), __float2half_rn(c1));
                if (r1 < M) *(__half2*)(Cout + (size_t)r1 * N_TOT + n) =
                    __halves2half2(__float2half_rn(c2), __float2half_rn(c3));
            } else {
                if (n < 128) {
                    if (r0 < M) *(__half2*)(OutH + (size_t)r0 * 128 + n) =
                        __halves2half2(__float2half_rn(a[0]), __float2half_rn(a[1]));
                    if (r1 < M) *(__half2*)(OutH + (size_t)r1 * 128 + n) =
                        __halves2half2(__float2half_rn(a[2]), __float2half_rn(a[3]));
                } else {
                    int nn = n - 128;
                    float2 bb = *(const float2*)(bias + nn);
                    if (r0 < M) *(float2*)(OutF2 + (size_t)r0 * 128 + nn) =
                        make_float2(a[0] + bb.x, a[1] + bb.y);
                    if (r1 < M) *(float2*)(OutF2 + (size_t)r1 * 128 + nn) =
                        make_float2(a[2] + bb.x, a[3] + bb.y);
                }
            }
        }
    }
}

// ---------------------------------------------------------------------------
// Launch
// ---------------------------------------------------------------------------
extern "C" void kernel_launch(void* const* d_in, const int* in_sizes, int n_in,
                              void* d_out, int out_size)
{
    const float* x   = (const float*)d_in[0];
    const int*   ei  = (const int*)d_in[1];     // int32 (JAX x64 disabled)
    const float* W1l = (const float*)d_in[2];
    const float* b1  = (const float*)d_in[3];
    const float* W1r = (const float*)d_in[4];
    const float* W2l = (const float*)d_in[5];
    const float* b2  = (const float*)d_in[6];
    const float* W2r = (const float*)d_in[7];
    float*       out = (float*)d_out;

    const int* src = ei;
    const int* dst = ei + N_EDGES;

    __half *xh, *a1, *h, *wt1, *wt2, *y2l;
    cudaGetSymbolAddress((void**)&y2l, g_y2l);
    cudaGetSymbolAddress((void**)&xh,  g_x);
    cudaGetSymbolAddress((void**)&a1,  g_a1);
    cudaGetSymbolAddress((void**)&h,   g_h);
    cudaGetSymbolAddress((void**)&wt1, g_wt1);
    cudaGetSymbolAddress((void**)&wt2, g_wt2);

    auto gemm1 = sage_mma_warp<256, 2, 256, 0>;
    auto gemm2 = sage_mma_warp<256, 1, 256, 1>;
    cudaFuncSetAttribute(gemm1, cudaFuncAttributeMaxDynamicSharedMemorySize, MMA_SMEM_TOTAL);
    cudaFuncSetAttribute(gemm2, cudaFuncAttributeMaxDynamicSharedMemorySize, MMA_SMEM_TOTAL);

    int mgrid = (N_NODES + 127) / 128;

    // ---- prologue: hist + feature cvt + weight prep (one launch) ----
    prologue_kernel<<<(PRO_TOT + 255) / 256, 256>>>(dst, x, W1l, W1r, W2l, W2r);

    // ---- CSR scan + fill ----
    scan_stage1_kernel<<<NB_SCAN, 256>>>();
    scan_stage3_kernel<<<NB_SCAN, 256>>>();
    fill_kernel<<<(N_EDGES + 255) / 256, 256>>>(src, dst);

    // ---- layer 1: gather x -> a1, then [a1|x] @ wt1 -> h (fp16) ----
    {
        int warps_per_block = 8;
        int grid = (N_NODES + warps_per_block - 1) / warps_per_block;
        gather_f16_kernel<IN_C><<<grid, warps_per_block * 32>>>(xh, a1);
    }
    {
        dim3 grid(mgrid, 2);
        gemm1<<<grid, 256, MMA_SMEM_TOTAL>>>(
            a1, xh, wt1, b1, nullptr, nullptr, h, N_NODES);
    }

    // ---- layer 2 (gather commuted): h @ [W2l|W2r] -> y2l (fp16), out(+b2) ----
    {
        dim3 grid(mgrid, 2);
        gemm2<<<grid, 256, MMA_SMEM_TOTAL>>>(
            h, nullptr, wt2, b2, y2l, out, nullptr, N_NODES);
    }
    // out += mean-gather(y2l)
    {
        int warps_per_block = 8;
        int grid = (N_NODES + warps_per_block - 1) / warps_per_block;
        gather_acc_kernel<<<grid, warps_per_block * 32>>>(y2l, out);
    }
}